// round 2
// baseline (speedup 1.0000x reference)
#include <cuda_runtime.h>
#include <math.h>

// ---- problem dims (static per reference setup_inputs) ----
#define BB   4
#define SS   512
#define VV   50257
#define DD   768
#define HH   12
#define DHH  64
#define NLAYER 2
#define DFFN 3072
#define LAT_START 64
#define NLAT 6
#define ATT_SCALE 0.125f   // 1/sqrt(64)

// ---- scratch (device globals; no allocations allowed) ----
static __device__ float g_embeds[BB*SS*DD];
static __device__ float g_X   [BB*SS*DD];
static __device__ float g_H   [BB*SS*DD];
static __device__ float g_QKV [BB*SS*3*DD];
static __device__ float g_CTX [BB*SS*DD];
static __device__ float g_G   [BB*SS*DFFN];
static __device__ float g_nll [BB*(SS-1)];

__device__ __forceinline__ float warpReduceSum(float v) {
    #pragma unroll
    for (int o = 16; o; o >>= 1) v += __shfl_xor_sync(0xffffffffu, v, o);
    return v;
}
__device__ __forceinline__ float warpReduceMax(float v) {
    #pragma unroll
    for (int o = 16; o; o >>= 1) v = fmaxf(v, __shfl_xor_sync(0xffffffffu, v, o));
    return v;
}

// ---- embeds = wte[input_ids]  (full [B,S,D], once) ----
__global__ void embed_init_kernel(const int* __restrict__ ids, const float* __restrict__ wte) {
    int idx = blockIdx.x * blockDim.x + threadIdx.x;
    if (idx >= BB*SS*DD) return;
    int r = idx / DD, d = idx - r*DD;
    g_embeds[idx] = wte[(size_t)ids[r]*DD + d];
}

// ---- X[b*T+t, :] = embeds[b, t, :] + wpe[pos_ids[b,t], :]  (compact prefix) ----
__global__ void embed_pos_kernel(const int* __restrict__ pos_ids, const float* __restrict__ wpe, int T) {
    int idx = blockIdx.x * blockDim.x + threadIdx.x;
    int total = BB*T*DD;
    if (idx >= total) return;
    int r = idx / DD, d = idx - r*DD;
    int b = r / T, t = r - b*T;
    int pos = pos_ids[b*SS + t];
    g_X[idx] = g_embeds[((size_t)b*SS + t)*DD + d] + wpe[(size_t)pos*DD + d];
}

// ---- LayerNorm: one block (256 thr) per row of 768 ----
__global__ void ln_kernel(const float* __restrict__ in, float* __restrict__ out,
                          const float* __restrict__ gam, const float* __restrict__ bet, int rows) {
    int r = blockIdx.x;
    if (r >= rows) return;
    const float* x = in + (size_t)r*DD;
    int tid = threadIdx.x;
    float x0 = x[tid], x1 = x[tid+256], x2 = x[tid+512];
    __shared__ float sh[8];
    float s = warpReduceSum(x0 + x1 + x2);
    if ((tid & 31) == 0) sh[tid >> 5] = s;
    __syncthreads();
    if (tid == 0) { float t = 0.f; for (int i = 0; i < 8; i++) t += sh[i]; sh[0] = t * (1.f/DD); }
    __syncthreads();
    float mean = sh[0];
    float d0 = x0 - mean, d1 = x1 - mean, d2 = x2 - mean;
    __syncthreads();
    float q = warpReduceSum(d0*d0 + d1*d1 + d2*d2);
    if ((tid & 31) == 0) sh[tid >> 5] = q;
    __syncthreads();
    if (tid == 0) { float t = 0.f; for (int i = 0; i < 8; i++) t += sh[i]; sh[0] = rsqrtf(t*(1.f/DD) + 1e-5f); }
    __syncthreads();
    float rstd = sh[0];
    float* o = out + (size_t)r*DD;
    o[tid]     = d0*rstd*gam[tid]     + bet[tid];
    o[tid+256] = d1*rstd*gam[tid+256] + bet[tid+256];
    o[tid+512] = d2*rstd*gam[tid+512] + bet[tid+512];
}

__device__ __forceinline__ float gelu_tanh(float u) {
    return 0.5f*u*(1.f + tanhf(0.7978845608028654f*(u + 0.044715f*u*u*u)));
}

// ---- generic SGEMM: C = act(A[M,K] @ W[K,N] + bias) (+ res) ----
// 128x64x16 tile, 256 threads, 8x4 micro-tile.
template<int ACT, int HASRES>
__global__ void __launch_bounds__(256) gemm_nn(const float* __restrict__ A, const float* __restrict__ W,
                                               const float* __restrict__ bias, const float* res,
                                               float* C, int M, int N, int K) {
    __shared__ float As[16][128];
    __shared__ float Bs[16][64];
    int tid = threadIdx.x;
    int row0 = blockIdx.y * 128, col0 = blockIdx.x * 64;
    int tx = tid & 15, ty = tid >> 4;
    float acc[8][4];
    #pragma unroll
    for (int i = 0; i < 8; i++)
        #pragma unroll
        for (int j = 0; j < 4; j++) acc[i][j] = 0.f;

    for (int k0 = 0; k0 < K; k0 += 16) {
        #pragma unroll
        for (int i = 0; i < 2; i++) {
            int idx = tid + i*256;
            int r = idx >> 2, c4 = idx & 3;
            int gr = row0 + r;
            float4 v = make_float4(0.f,0.f,0.f,0.f);
            if (gr < M) v = *(const float4*)(A + (size_t)gr*K + k0 + c4*4);
            As[c4*4+0][r] = v.x; As[c4*4+1][r] = v.y; As[c4*4+2][r] = v.z; As[c4*4+3][r] = v.w;
        }
        {
            int kk = tid >> 4, n4 = tid & 15;
            int gn = col0 + n4*4;
            float4 v = make_float4(0.f,0.f,0.f,0.f);
            if (gn + 3 < N) v = *(const float4*)(W + (size_t)(k0+kk)*N + gn);
            else {
                float* vp = (float*)&v;
                for (int j = 0; j < 4; j++) if (gn + j < N) vp[j] = W[(size_t)(k0+kk)*N + gn + j];
            }
            *(float4*)&Bs[kk][n4*4] = v;
        }
        __syncthreads();
        #pragma unroll
        for (int k = 0; k < 16; k++) {
            float4 a0 = *(const float4*)&As[k][ty*8];
            float4 a1 = *(const float4*)&As[k][ty*8+4];
            float4 b0 = *(const float4*)&Bs[k][tx*4];
            float av[8] = {a0.x,a0.y,a0.z,a0.w,a1.x,a1.y,a1.z,a1.w};
            float bv[4] = {b0.x,b0.y,b0.z,b0.w};
            #pragma unroll
            for (int i = 0; i < 8; i++)
                #pragma unroll
                for (int j = 0; j < 4; j++) acc[i][j] = fmaf(av[i], bv[j], acc[i][j]);
        }
        __syncthreads();
    }
    #pragma unroll
    for (int i = 0; i < 8; i++) {
        int gr = row0 + ty*8 + i;
        if (gr >= M) break;
        #pragma unroll
        for (int j = 0; j < 4; j++) {
            int gn = col0 + tx*4 + j;
            if (gn >= N) continue;
            float v = acc[i][j] + bias[gn];
            if (ACT == 1) v = gelu_tanh(v);
            if (HASRES)  v += res[(size_t)gr*N + gn];
            C[(size_t)gr*N + gn] = v;
        }
    }
}

// ---- fused attention: one warp per query row, online softmax ----
__global__ void attn_kernel(const int* __restrict__ amask, int T) {
    int warp = threadIdx.x >> 5, lane = threadIdx.x & 31;
    int q = blockIdx.x * 4 + warp;
    if (q >= T) return;
    int bh = blockIdx.y;
    int b = bh / HH, h = bh - b*HH;
    const float* qb = g_QKV + ((size_t)(b*T + q))*(3*DD) + h*DHH;
    float2 qv = *(const float2*)&qb[lane*2];
    qv.x *= ATT_SCALE; qv.y *= ATT_SCALE;
    float m = -1e30f, denom = 0.f;
    float2 acc = make_float2(0.f, 0.f);
    for (int j = 0; j <= q; j++) {
        const float* kb = g_QKV + ((size_t)(b*T + j))*(3*DD) + DD + h*DHH;
        float2 kv = *(const float2*)&kb[lane*2];
        float s = qv.x*kv.x + qv.y*kv.y;
        s = warpReduceSum(s);
        if (amask[b*SS + j] == 0) s = -1e9f;
        float mn = fmaxf(m, s);
        float alpha = __expf(m - mn);
        float p = __expf(s - mn);
        denom = denom*alpha + p;
        const float* vb = kb + DD;
        float2 vv = *(const float2*)&vb[lane*2];
        acc.x = acc.x*alpha + p*vv.x;
        acc.y = acc.y*alpha + p*vv.y;
        m = mn;
    }
    float inv = 1.f / denom;
    float2 o = make_float2(acc.x*inv, acc.y*inv);
    *(float2*)&g_CTX[((size_t)(b*T + q))*DD + h*DHH + lane*2] = o;
}

// ---- lm_head (big M): logits[b, t, :] = H[b*T+t, :] @ wte^T, rows t in [a,T) ----
__global__ void __launch_bounds__(256) gemm_lmhead(const float* __restrict__ Hbuf, const float* __restrict__ wte,
                                                   float* out, int T, int a) {
    int QL = T - a;
    int M = BB * QL;
    __shared__ float As[16][128];
    __shared__ float Bs[16][64];
    int tid = threadIdx.x;
    int row0 = blockIdx.y * 128, col0 = blockIdx.x * 64;
    int tx = tid & 15, ty = tid >> 4;
    float acc[8][4];
    #pragma unroll
    for (int i = 0; i < 8; i++)
        #pragma unroll
        for (int j = 0; j < 4; j++) acc[i][j] = 0.f;

    for (int k0 = 0; k0 < DD; k0 += 16) {
        #pragma unroll
        for (int i = 0; i < 2; i++) {
            int idx = tid + i*256;
            int r = idx >> 2, c4 = idx & 3;
            int gr = row0 + r;
            float4 v = make_float4(0.f,0.f,0.f,0.f);
            if (gr < M) {
                int bb = gr / QL, t = a + gr - bb*QL;
                v = *(const float4*)(Hbuf + ((size_t)bb*T + t)*DD + k0 + c4*4);
            }
            As[c4*4+0][r] = v.x; As[c4*4+1][r] = v.y; As[c4*4+2][r] = v.z; As[c4*4+3][r] = v.w;
        }
        {
            int n = tid >> 2, k4 = tid & 3;
            int gn = col0 + n;
            float4 v = make_float4(0.f,0.f,0.f,0.f);
            if (gn < VV) v = *(const float4*)(wte + (size_t)gn*DD + k0 + k4*4);
            Bs[k4*4+0][n] = v.x; Bs[k4*4+1][n] = v.y; Bs[k4*4+2][n] = v.z; Bs[k4*4+3][n] = v.w;
        }
        __syncthreads();
        #pragma unroll
        for (int k = 0; k < 16; k++) {
            float4 a0 = *(const float4*)&As[k][ty*8];
            float4 a1 = *(const float4*)&As[k][ty*8+4];
            float4 b0 = *(const float4*)&Bs[k][tx*4];
            float av[8] = {a0.x,a0.y,a0.z,a0.w,a1.x,a1.y,a1.z,a1.w};
            float bv[4] = {b0.x,b0.y,b0.z,b0.w};
            #pragma unroll
            for (int i = 0; i < 8; i++)
                #pragma unroll
                for (int j = 0; j < 4; j++) acc[i][j] = fmaf(av[i], bv[j], acc[i][j]);
        }
        __syncthreads();
    }
    #pragma unroll
    for (int i = 0; i < 8; i++) {
        int gr = row0 + ty*8 + i;
        if (gr >= M) break;
        int bb = gr / QL, t = a + gr - bb*QL;
        float* cr = out + ((size_t)bb*SS + t)*VV;
        #pragma unroll
        for (int j = 0; j < 4; j++) {
            int gn = col0 + tx*4 + j;
            if (gn < VV) cr[gn] = acc[i][j];
        }
    }
}

// ---- lm_head for single-query passes (M = B = 4): warp per vocab row ----
__global__ void lmhead_small(const float* __restrict__ Hbuf, const float* __restrict__ wte,
                             float* out, int T, int a) {
    __shared__ float hsh[BB][DD];
    int tid = threadIdx.x;
    for (int i = tid; i < BB*DD; i += 256) {
        int b = i / DD, d = i - b*DD;
        hsh[b][d] = Hbuf[((size_t)b*T + a)*DD + d];
    }
    __syncthreads();
    int warp = tid >> 5, lane = tid & 31;
    int n = blockIdx.x * 8 + warp;
    if (n >= VV) return;
    const float* wr = wte + (size_t)n*DD;
    float a0 = 0.f, a1 = 0.f, a2 = 0.f, a3 = 0.f;
    for (int k = lane; k < DD; k += 32) {
        float w = wr[k];
        a0 = fmaf(w, hsh[0][k], a0);
        a1 = fmaf(w, hsh[1][k], a1);
        a2 = fmaf(w, hsh[2][k], a2);
        a3 = fmaf(w, hsh[3][k], a3);
    }
    a0 = warpReduceSum(a0); a1 = warpReduceSum(a1);
    a2 = warpReduceSum(a2); a3 = warpReduceSum(a3);
    if (lane == 0) {
        out[((size_t)0*SS + a)*VV + n] = a0;
        out[((size_t)1*SS + a)*VV + n] = a1;
        out[((size_t)2*SS + a)*VV + n] = a2;
        out[((size_t)3*SS + a)*VV + n] = a3;
    }
}

// ---- latent update: embeds[b, slot, :] = H[b*T + (T-1), :] ----
__global__ void latent_update_kernel(int slot, int T) {
    int idx = blockIdx.x * blockDim.x + threadIdx.x;
    if (idx >= BB*DD) return;
    int b = idx / DD, d = idx - b*DD;
    g_embeds[((size_t)b*SS + slot)*DD + d] = g_H[((size_t)b*T + (T-1))*DD + d];
}

// ---- loss: per-row logsumexp + NLL ----
__global__ void loss_row_kernel(const float* __restrict__ logits, const int* __restrict__ labels) {
    int r = blockIdx.x;                   // 0 .. B*(S-1)-1
    int b = r / (SS-1), t = r - b*(SS-1);
    const float* x = logits + ((size_t)(b*SS + t))*VV;
    int tid = threadIdx.x;
    __shared__ float sh[8];
    float mx = -1e30f;
    for (int i = tid; i < VV; i += 256) mx = fmaxf(mx, x[i]);
    mx = warpReduceMax(mx);
    if ((tid & 31) == 0) sh[tid >> 5] = mx;
    __syncthreads();
    if (tid == 0) { float m = sh[0]; for (int i = 1; i < 8; i++) m = fmaxf(m, sh[i]); sh[0] = m; }
    __syncthreads();
    mx = sh[0];
    __syncthreads();
    float se = 0.f;
    for (int i = tid; i < VV; i += 256) se += __expf(x[i] - mx);
    se = warpReduceSum(se);
    if ((tid & 31) == 0) sh[tid >> 5] = se;
    __syncthreads();
    if (tid == 0) {
        float s = 0.f; for (int i = 0; i < 8; i++) s += sh[i];
        int lab = labels[b*SS + t + 1];
        g_nll[r] = logf(s) + mx - x[lab];
    }
}

__global__ void loss_final_kernel(float* out) {
    int tid = threadIdx.x;
    const int NR = BB*(SS-1);
    __shared__ float sh[8];
    float s = 0.f;
    for (int i = tid; i < NR; i += 256) s += g_nll[i];
    s = warpReduceSum(s);
    if ((tid & 31) == 0) sh[tid >> 5] = s;
    __syncthreads();
    if (tid == 0) {
        float t = 0.f; for (int i = 0; i < 8; i++) t += sh[i];
        out[0] = t / (float)NR;
    }
}

// ---- host orchestration ----
extern "C" void kernel_launch(void* const* d_in, const int* in_sizes, int n_in,
                              void* d_out, int out_size) {
    const int*   input_ids = (const int*)d_in[0];
    const int*   amask     = (const int*)d_in[1];
    const int*   labels    = (const int*)d_in[2];
    const int*   pos_ids   = (const int*)d_in[3];
    const float* wte   = (const float*)d_in[4];
    const float* wpe   = (const float*)d_in[5];
    const float* ln1_g = (const float*)d_in[6];
    const float* ln1_b = (const float*)d_in[7];
    const float* Wqkv  = (const float*)d_in[8];
    const float* bqkv  = (const float*)d_in[9];
    const float* Wo    = (const float*)d_in[10];
    const float* bo    = (const float*)d_in[11];
    const float* ln2_g = (const float*)d_in[12];
    const float* ln2_b = (const float*)d_in[13];
    const float* W1    = (const float*)d_in[14];
    const float* b1    = (const float*)d_in[15];
    const float* W2    = (const float*)d_in[16];
    const float* b2    = (const float*)d_in[17];
    const float* lnf_g = (const float*)d_in[18];
    const float* lnf_b = (const float*)d_in[19];
    // d_in[20] = latent_start (64), d_in[21] = n_latent (6): static, hardcoded.

    float* out    = (float*)d_out;
    float* logits = out + 1;

    float *pX, *pH, *pQKV, *pCTX, *pG;
    cudaGetSymbolAddress((void**)&pX,   g_X);
    cudaGetSymbolAddress((void**)&pH,   g_H);
    cudaGetSymbolAddress((void**)&pQKV, g_QKV);
    cudaGetSymbolAddress((void**)&pCTX, g_CTX);
    cudaGetSymbolAddress((void**)&pG,   g_G);

    embed_init_kernel<<<(BB*SS*DD + 255)/256, 256>>>(input_ids, wte);

    const int Ts[7] = {64, 65, 66, 67, 68, 69, 512};
    const int As[7] = {0,  64, 65, 66, 67, 68, 69};

    for (int p = 0; p < 7; p++) {
        int T = Ts[p], a = As[p];
        int M = BB * T;

        embed_pos_kernel<<<(M*DD + 255)/256, 256>>>(pos_ids, wpe, T);

        for (int l = 0; l < NLAYER; l++) {
            const float* Wq  = Wqkv + (size_t)l*DD*3*DD;
            const float* bq  = bqkv + (size_t)l*3*DD;
            const float* Wol = Wo   + (size_t)l*DD*DD;
            const float* bol = bo   + (size_t)l*DD;
            const float* W1l = W1   + (size_t)l*DD*DFFN;
            const float* b1l = b1   + (size_t)l*DFFN;
            const float* W2l = W2   + (size_t)l*DFFN*DD;
            const float* b2l = b2   + (size_t)l*DD;

            ln_kernel<<<M, 256>>>(pX, pH, ln1_g + l*DD, ln1_b + l*DD, M);

            gemm_nn<0,0><<<dim3((3*DD + 63)/64, (M + 127)/128), 256>>>(
                pH, Wq, bq, nullptr, pQKV, M, 3*DD, DD);

            attn_kernel<<<dim3((T + 3)/4, BB*HH), 128>>>(amask, T);

            gemm_nn<0,1><<<dim3((DD + 63)/64, (M + 127)/128), 256>>>(
                pCTX, Wol, bol, pX, pX, M, DD, DD);

            ln_kernel<<<M, 256>>>(pX, pH, ln2_g + l*DD, ln2_b + l*DD, M);

            gemm_nn<1,0><<<dim3((DFFN + 63)/64, (M + 127)/128), 256>>>(
                pH, W1l, b1l, nullptr, pG, M, DFFN, DD);

            gemm_nn<0,1><<<dim3((DD + 63)/64, (M + 127)/128), 256>>>(
                pG, W2l, b2l, pX, pX, M, DD, DFFN);
        }

        ln_kernel<<<M, 256>>>(pX, pH, lnf_g, lnf_b, M);

        int QL = T - a;
        if (QL == 1) {
            lmhead_small<<<(VV + 7)/8, 256>>>(pH, wte, logits, T, a);
        } else {
            gemm_lmhead<<<dim3((VV + 63)/64, (BB*QL + 127)/128), 256>>>(pH, wte, logits, T, a);
        }

        if (p < NLAT) {
            latent_update_kernel<<<(BB*DD + 255)/256, 256>>>(LAT_START + p, T);
        }
    }

    loss_row_kernel<<<BB*(SS-1), 256>>>(logits, labels);
    loss_final_kernel<<<1, 256>>>(out);
}

// round 5
// speedup vs baseline: 1.0014x; 1.0014x over previous
#include <cuda_runtime.h>
#include <math.h>

// ---- problem dims (static per reference setup_inputs) ----
#define BB   4
#define SS   512
#define VV   50257
#define DD   768
#define HH   12
#define DHH  64
#define NLAYER 2
#define DFFN 3072
#define LAT_START 64
#define NLAT 6
#define ATT_SCALE 0.125f   // 1/sqrt(64)

// ---- scratch (device globals; no allocations allowed) ----
static __device__ float g_embeds[BB*SS*DD];
static __device__ float g_X   [BB*SS*DD];
static __device__ float g_H   [BB*SS*DD];
static __device__ float g_QKV [BB*SS*3*DD];
static __device__ float g_CTX [BB*SS*DD];
static __device__ float g_G   [BB*SS*DFFN];
static __device__ float g_nll [BB*(SS-1)];

__device__ __forceinline__ float warpReduceSum(float v) {
    #pragma unroll
    for (int o = 16; o; o >>= 1) v += __shfl_xor_sync(0xffffffffu, v, o);
    return v;
}
__device__ __forceinline__ float warpReduceMax(float v) {
    #pragma unroll
    for (int o = 16; o; o >>= 1) v = fmaxf(v, __shfl_xor_sync(0xffffffffu, v, o));
    return v;
}

// ---- embeds = wte[input_ids]  (full [B,S,D], once) ----
__global__ void embed_init_kernel(const int* __restrict__ ids, const float* __restrict__ wte) {
    int idx = blockIdx.x * blockDim.x + threadIdx.x;
    if (idx >= BB*SS*DD) return;
    int r = idx / DD, d = idx - r*DD;
    g_embeds[idx] = wte[(size_t)ids[r]*DD + d];
}

// ---- X[b*T+t, :] = embeds[b, t, :] + wpe[pos_ids[b,t], :]  (compact prefix) ----
__global__ void embed_pos_kernel(const int* __restrict__ pos_ids, const float* __restrict__ wpe, int T) {
    int idx = blockIdx.x * blockDim.x + threadIdx.x;
    int total = BB*T*DD;
    if (idx >= total) return;
    int r = idx / DD, d = idx - r*DD;
    int b = r / T, t = r - b*T;
    int pos = pos_ids[b*SS + t];
    g_X[idx] = g_embeds[((size_t)b*SS + t)*DD + d] + wpe[(size_t)pos*DD + d];
}

// ---- LayerNorm: one block (256 thr) per row of 768 ----
__global__ void ln_kernel(const float* __restrict__ in, float* __restrict__ out,
                          const float* __restrict__ gam, const float* __restrict__ bet, int rows) {
    int r = blockIdx.x;
    if (r >= rows) return;
    const float* x = in + (size_t)r*DD;
    int tid = threadIdx.x;
    float x0 = x[tid], x1 = x[tid+256], x2 = x[tid+512];
    __shared__ float sh[8];
    float s = warpReduceSum(x0 + x1 + x2);
    if ((tid & 31) == 0) sh[tid >> 5] = s;
    __syncthreads();
    if (tid == 0) { float t = 0.f; for (int i = 0; i < 8; i++) t += sh[i]; sh[0] = t * (1.f/DD); }
    __syncthreads();
    float mean = sh[0];
    float d0 = x0 - mean, d1 = x1 - mean, d2 = x2 - mean;
    __syncthreads();
    float q = warpReduceSum(d0*d0 + d1*d1 + d2*d2);
    if ((tid & 31) == 0) sh[tid >> 5] = q;
    __syncthreads();
    if (tid == 0) { float t = 0.f; for (int i = 0; i < 8; i++) t += sh[i]; sh[0] = rsqrtf(t*(1.f/DD) + 1e-5f); }
    __syncthreads();
    float rstd = sh[0];
    float* o = out + (size_t)r*DD;
    o[tid]     = d0*rstd*gam[tid]     + bet[tid];
    o[tid+256] = d1*rstd*gam[tid+256] + bet[tid+256];
    o[tid+512] = d2*rstd*gam[tid+512] + bet[tid+512];
}

__device__ __forceinline__ float gelu_tanh(float u) {
    return 0.5f*u*(1.f + tanhf(0.7978845608028654f*(u + 0.044715f*u*u*u)));
}

// ---- generic SGEMM: C = act(A[M,K] @ W[K,N] + bias) (+ res) ----
// 128x64x16 tile, 256 threads, 8x4 micro-tile.
template<int ACT, int HASRES>
__global__ void __launch_bounds__(256) gemm_nn(const float* __restrict__ A, const float* __restrict__ W,
                                               const float* __restrict__ bias, const float* res,
                                               float* C, int M, int N, int K) {
    __shared__ float As[16][128];
    __shared__ float Bs[16][64];
    int tid = threadIdx.x;
    int row0 = blockIdx.y * 128, col0 = blockIdx.x * 64;
    int tx = tid & 15, ty = tid >> 4;
    float acc[8][4];
    #pragma unroll
    for (int i = 0; i < 8; i++)
        #pragma unroll
        for (int j = 0; j < 4; j++) acc[i][j] = 0.f;

    for (int k0 = 0; k0 < K; k0 += 16) {
        #pragma unroll
        for (int i = 0; i < 2; i++) {
            int idx = tid + i*256;
            int r = idx >> 2, c4 = idx & 3;
            int gr = row0 + r;
            float4 v = make_float4(0.f,0.f,0.f,0.f);
            if (gr < M) v = *(const float4*)(A + (size_t)gr*K + k0 + c4*4);
            As[c4*4+0][r] = v.x; As[c4*4+1][r] = v.y; As[c4*4+2][r] = v.z; As[c4*4+3][r] = v.w;
        }
        {
            int kk = tid >> 4, n4 = tid & 15;
            int gn = col0 + n4*4;
            float4 v = make_float4(0.f,0.f,0.f,0.f);
            if (gn + 3 < N) v = *(const float4*)(W + (size_t)(k0+kk)*N + gn);
            else {
                float* vp = (float*)&v;
                for (int j = 0; j < 4; j++) if (gn + j < N) vp[j] = W[(size_t)(k0+kk)*N + gn + j];
            }
            *(float4*)&Bs[kk][n4*4] = v;
        }
        __syncthreads();
        #pragma unroll
        for (int k = 0; k < 16; k++) {
            float4 a0 = *(const float4*)&As[k][ty*8];
            float4 a1 = *(const float4*)&As[k][ty*8+4];
            float4 b0 = *(const float4*)&Bs[k][tx*4];
            float av[8] = {a0.x,a0.y,a0.z,a0.w,a1.x,a1.y,a1.z,a1.w};
            float bv[4] = {b0.x,b0.y,b0.z,b0.w};
            #pragma unroll
            for (int i = 0; i < 8; i++)
                #pragma unroll
                for (int j = 0; j < 4; j++) acc[i][j] = fmaf(av[i], bv[j], acc[i][j]);
        }
        __syncthreads();
    }
    #pragma unroll
    for (int i = 0; i < 8; i++) {
        int gr = row0 + ty*8 + i;
        if (gr >= M) break;
        #pragma unroll
        for (int j = 0; j < 4; j++) {
            int gn = col0 + tx*4 + j;
            if (gn >= N) continue;
            float v = acc[i][j] + bias[gn];
            if (ACT == 1) v = gelu_tanh(v);
            if (HASRES)  v += res[(size_t)gr*N + gn];
            C[(size_t)gr*N + gn] = v;
        }
    }
}

// ---- fused attention: one warp per query row, online softmax ----
__global__ void attn_kernel(const int* __restrict__ amask, int T) {
    int warp = threadIdx.x >> 5, lane = threadIdx.x & 31;
    int q = blockIdx.x * 4 + warp;
    if (q >= T) return;
    int bh = blockIdx.y;
    int b = bh / HH, h = bh - b*HH;
    const float* qb = g_QKV + ((size_t)(b*T + q))*(3*DD) + h*DHH;
    float2 qv = *(const float2*)&qb[lane*2];
    qv.x *= ATT_SCALE; qv.y *= ATT_SCALE;
    float m = -1e30f, denom = 0.f;
    float2 acc = make_float2(0.f, 0.f);
    for (int j = 0; j <= q; j++) {
        const float* kb = g_QKV + ((size_t)(b*T + j))*(3*DD) + DD + h*DHH;
        float2 kv = *(const float2*)&kb[lane*2];
        float s = qv.x*kv.x + qv.y*kv.y;
        s = warpReduceSum(s);
        if (amask[b*SS + j] == 0) s = -1e9f;
        float mn = fmaxf(m, s);
        float alpha = __expf(m - mn);
        float p = __expf(s - mn);
        denom = denom*alpha + p;
        const float* vb = kb + DD;
        float2 vv = *(const float2*)&vb[lane*2];
        acc.x = acc.x*alpha + p*vv.x;
        acc.y = acc.y*alpha + p*vv.y;
        m = mn;
    }
    float inv = 1.f / denom;
    float2 o = make_float2(acc.x*inv, acc.y*inv);
    *(float2*)&g_CTX[((size_t)(b*T + q))*DD + h*DHH + lane*2] = o;
}

// ---- lm_head (big M): logits[b, t, :] = H[b*T+t, :] @ wte^T, rows t in [a,T) ----
__global__ void __launch_bounds__(256) gemm_lmhead(const float* __restrict__ Hbuf, const float* __restrict__ wte,
                                                   float* out, int T, int a) {
    int QL = T - a;
    int M = BB * QL;
    __shared__ float As[16][128];
    __shared__ float Bs[16][64];
    int tid = threadIdx.x;
    int row0 = blockIdx.y * 128, col0 = blockIdx.x * 64;
    int tx = tid & 15, ty = tid >> 4;
    float acc[8][4];
    #pragma unroll
    for (int i = 0; i < 8; i++)
        #pragma unroll
        for (int j = 0; j < 4; j++) acc[i][j] = 0.f;

    for (int k0 = 0; k0 < DD; k0 += 16) {
        #pragma unroll
        for (int i = 0; i < 2; i++) {
            int idx = tid + i*256;
            int r = idx >> 2, c4 = idx & 3;
            int gr = row0 + r;
            float4 v = make_float4(0.f,0.f,0.f,0.f);
            if (gr < M) {
                int bb = gr / QL, t = a + gr - bb*QL;
                v = *(const float4*)(Hbuf + ((size_t)bb*T + t)*DD + k0 + c4*4);
            }
            As[c4*4+0][r] = v.x; As[c4*4+1][r] = v.y; As[c4*4+2][r] = v.z; As[c4*4+3][r] = v.w;
        }
        {
            int n = tid >> 2, k4 = tid & 3;
            int gn = col0 + n;
            float4 v = make_float4(0.f,0.f,0.f,0.f);
            if (gn < VV) v = *(const float4*)(wte + (size_t)gn*DD + k0 + k4*4);
            Bs[k4*4+0][n] = v.x; Bs[k4*4+1][n] = v.y; Bs[k4*4+2][n] = v.z; Bs[k4*4+3][n] = v.w;
        }
        __syncthreads();
        #pragma unroll
        for (int k = 0; k < 16; k++) {
            float4 a0 = *(const float4*)&As[k][ty*8];
            float4 a1 = *(const float4*)&As[k][ty*8+4];
            float4 b0 = *(const float4*)&Bs[k][tx*4];
            float av[8] = {a0.x,a0.y,a0.z,a0.w,a1.x,a1.y,a1.z,a1.w};
            float bv[4] = {b0.x,b0.y,b0.z,b0.w};
            #pragma unroll
            for (int i = 0; i < 8; i++)
                #pragma unroll
                for (int j = 0; j < 4; j++) acc[i][j] = fmaf(av[i], bv[j], acc[i][j]);
        }
        __syncthreads();
    }
    #pragma unroll
    for (int i = 0; i < 8; i++) {
        int gr = row0 + ty*8 + i;
        if (gr >= M) break;
        int bb = gr / QL, t = a + gr - bb*QL;
        float* cr = out + ((size_t)bb*SS + t)*VV;
        #pragma unroll
        for (int j = 0; j < 4; j++) {
            int gn = col0 + tx*4 + j;
            if (gn < VV) cr[gn] = acc[i][j];
        }
    }
}

// ---- lm_head for single-query passes (M = B = 4): warp per vocab row ----
__global__ void lmhead_small(const float* __restrict__ Hbuf, const float* __restrict__ wte,
                             float* out, int T, int a) {
    __shared__ float hsh[BB][DD];
    int tid = threadIdx.x;
    for (int i = tid; i < BB*DD; i += 256) {
        int b = i / DD, d = i - b*DD;
        hsh[b][d] = Hbuf[((size_t)b*T + a)*DD + d];
    }
    __syncthreads();
    int warp = tid >> 5, lane = tid & 31;
    int n = blockIdx.x * 8 + warp;
    if (n >= VV) return;
    const float* wr = wte + (size_t)n*DD;
    float a0 = 0.f, a1 = 0.f, a2 = 0.f, a3 = 0.f;
    for (int k = lane; k < DD; k += 32) {
        float w = wr[k];
        a0 = fmaf(w, hsh[0][k], a0);
        a1 = fmaf(w, hsh[1][k], a1);
        a2 = fmaf(w, hsh[2][k], a2);
        a3 = fmaf(w, hsh[3][k], a3);
    }
    a0 = warpReduceSum(a0); a1 = warpReduceSum(a1);
    a2 = warpReduceSum(a2); a3 = warpReduceSum(a3);
    if (lane == 0) {
        out[((size_t)0*SS + a)*VV + n] = a0;
        out[((size_t)1*SS + a)*VV + n] = a1;
        out[((size_t)2*SS + a)*VV + n] = a2;
        out[((size_t)3*SS + a)*VV + n] = a3;
    }
}

// ---- latent update: embeds[b, slot, :] = H[b*T + (T-1), :] ----
__global__ void latent_update_kernel(int slot, int T) {
    int idx = blockIdx.x * blockDim.x + threadIdx.x;
    if (idx >= BB*DD) return;
    int b = idx / DD, d = idx - b*DD;
    g_embeds[((size_t)b*SS + slot)*DD + d] = g_H[((size_t)b*T + (T-1))*DD + d];
}

// ---- loss: per-row logsumexp + NLL ----
__global__ void loss_row_kernel(const float* __restrict__ logits, const int* __restrict__ labels) {
    int r = blockIdx.x;                   // 0 .. B*(S-1)-1
    int b = r / (SS-1), t = r - b*(SS-1);
    const float* x = logits + ((size_t)(b*SS + t))*VV;
    int tid = threadIdx.x;
    __shared__ float sh[8];
    float mx = -1e30f;
    for (int i = tid; i < VV; i += 256) mx = fmaxf(mx, x[i]);
    mx = warpReduceMax(mx);
    if ((tid & 31) == 0) sh[tid >> 5] = mx;
    __syncthreads();
    if (tid == 0) { float m = sh[0]; for (int i = 1; i < 8; i++) m = fmaxf(m, sh[i]); sh[0] = m; }
    __syncthreads();
    mx = sh[0];
    __syncthreads();
    float se = 0.f;
    for (int i = tid; i < VV; i += 256) se += __expf(x[i] - mx);
    se = warpReduceSum(se);
    if ((tid & 31) == 0) sh[tid >> 5] = se;
    __syncthreads();
    if (tid == 0) {
        float s = 0.f; for (int i = 0; i < 8; i++) s += sh[i];
        int lab = labels[b*SS + t + 1];
        g_nll[r] = logf(s) + mx - x[lab];
    }
}

__global__ void loss_final_kernel(float* out) {
    int tid = threadIdx.x;
    const int NR = BB*(SS-1);
    __shared__ float sh[8];
    float s = 0.f;
    for (int i = tid; i < NR; i += 256) s += g_nll[i];
    s = warpReduceSum(s);
    if ((tid & 31) == 0) sh[tid >> 5] = s;
    __syncthreads();
    if (tid == 0) {
        float t = 0.f; for (int i = 0; i < 8; i++) t += sh[i];
        out[0] = t / (float)NR;
    }
}

// ---- host orchestration ----
extern "C" void kernel_launch(void* const* d_in, const int* in_sizes, int n_in,
                              void* d_out, int out_size) {
    const int*   input_ids = (const int*)d_in[0];
    const int*   amask     = (const int*)d_in[1];
    const int*   labels    = (const int*)d_in[2];
    const int*   pos_ids   = (const int*)d_in[3];
    const float* wte   = (const float*)d_in[4];
    const float* wpe   = (const float*)d_in[5];
    const float* ln1_g = (const float*)d_in[6];
    const float* ln1_b = (const float*)d_in[7];
    const float* Wqkv  = (const float*)d_in[8];
    const float* bqkv  = (const float*)d_in[9];
    const float* Wo    = (const float*)d_in[10];
    const float* bo    = (const float*)d_in[11];
    const float* ln2_g = (const float*)d_in[12];
    const float* ln2_b = (const float*)d_in[13];
    const float* W1    = (const float*)d_in[14];
    const float* b1    = (const float*)d_in[15];
    const float* W2    = (const float*)d_in[16];
    const float* b2    = (const float*)d_in[17];
    const float* lnf_g = (const float*)d_in[18];
    const float* lnf_b = (const float*)d_in[19];
    // d_in[20] = latent_start (64), d_in[21] = n_latent (6): static, hardcoded.

    float* out    = (float*)d_out;
    float* logits = out + 1;

    float *pX, *pH, *pQKV, *pCTX, *pG;
    cudaGetSymbolAddress((void**)&pX,   g_X);
    cudaGetSymbolAddress((void**)&pH,   g_H);
    cudaGetSymbolAddress((void**)&pQKV, g_QKV);
    cudaGetSymbolAddress((void**)&pCTX, g_CTX);
    cudaGetSymbolAddress((void**)&pG,   g_G);

    embed_init_kernel<<<(BB*SS*DD + 255)/256, 256>>>(input_ids, wte);

    const int Ts[7] = {64, 65, 66, 67, 68, 69, 512};
    const int As[7] = {0,  64, 65, 66, 67, 68, 69};

    for (int p = 0; p < 7; p++) {
        int T = Ts[p], a = As[p];
        int M = BB * T;

        embed_pos_kernel<<<(M*DD + 255)/256, 256>>>(pos_ids, wpe, T);

        for (int l = 0; l < NLAYER; l++) {
            const float* Wq  = Wqkv + (size_t)l*DD*3*DD;
            const float* bq  = bqkv + (size_t)l*3*DD;
            const float* Wol = Wo   + (size_t)l*DD*DD;
            const float* bol = bo   + (size_t)l*DD;
            const float* W1l = W1   + (size_t)l*DD*DFFN;
            const float* b1l = b1   + (size_t)l*DFFN;
            const float* W2l = W2   + (size_t)l*DFFN*DD;
            const float* b2l = b2   + (size_t)l*DD;

            ln_kernel<<<M, 256>>>(pX, pH, ln1_g + l*DD, ln1_b + l*DD, M);

            gemm_nn<0,0><<<dim3((3*DD + 63)/64, (M + 127)/128), 256>>>(
                pH, Wq, bq, nullptr, pQKV, M, 3*DD, DD);

            attn_kernel<<<dim3((T + 3)/4, BB*HH), 128>>>(amask, T);

            gemm_nn<0,1><<<dim3((DD + 63)/64, (M + 127)/128), 256>>>(
                pCTX, Wol, bol, pX, pX, M, DD, DD);

            ln_kernel<<<M, 256>>>(pX, pH, ln2_g + l*DD, ln2_b + l*DD, M);

            gemm_nn<1,0><<<dim3((DFFN + 63)/64, (M + 127)/128), 256>>>(
                pH, W1l, b1l, nullptr, pG, M, DFFN, DD);

            gemm_nn<0,1><<<dim3((DD + 63)/64, (M + 127)/128), 256>>>(
                pG, W2l, b2l, pX, pX, M, DD, DFFN);
        }

        ln_kernel<<<M, 256>>>(pX, pH, lnf_g, lnf_b, M);

        int QL = T - a;
        if (QL == 1) {
            lmhead_small<<<(VV + 7)/8, 256>>>(pH, wte, logits, T, a);
        } else {
            gemm_lmhead<<<dim3((VV + 63)/64, (BB*QL + 127)/128), 256>>>(pH, wte, logits, T, a);
        }

        if (p < NLAT) {
            latent_update_kernel<<<(BB*DD + 255)/256, 256>>>(LAT_START + p, T);
        }
    }

    loss_row_kernel<<<BB*(SS-1), 256>>>(logits, labels);
    loss_final_kernel<<<1, 256>>>(out);
}

// round 10
// speedup vs baseline: 1.9334x; 1.9306x over previous
#include <cuda_runtime.h>
#include <math.h>

#define BB   4
#define SS   512
#define VV   50257
#define VPAD 50304
#define DD   768
#define HH   12
#define DHH  64
#define NLAYER 2
#define DFFN 3072
#define LAT_START 64
#define NLAT 6
#define ATT_SCALE 0.125f

// ---- scratch (device globals; zero-init; no allocations) ----
static __device__ float g_embeds[BB*SS*DD];
static __device__ float g_X   [BB*SS*DD];
static __device__ float g_H   [BB*SS*DD];
static __device__ float g_HID [BB*SS*DD];
static __device__ float g_QKV [BB*SS*3*DD];
static __device__ float g_CTX [BB*SS*DD];
static __device__ float g_G   [BB*SS*DFFN];
static __device__ float g_K   [NLAYER*BB*HH*SS*DHH];
static __device__ float g_V   [NLAYER*BB*HH*SS*DHH];
static __device__ float g_wteT[DD*VPAD];
static __device__ float g_part[24*4*DFFN];
static __device__ float g_sk  [8*1024*1024];
static __device__ float g_nll [BB*(SS-1)];

__device__ __forceinline__ float warpReduceSum(float v) {
    #pragma unroll
    for (int o = 16; o; o >>= 1) v += __shfl_xor_sync(0xffffffffu, v, o);
    return v;
}
__device__ __forceinline__ float warpReduceMax(float v) {
    #pragma unroll
    for (int o = 16; o; o >>= 1) v = fmaxf(v, __shfl_xor_sync(0xffffffffu, v, o));
    return v;
}
__device__ __forceinline__ float gelu_tanh(float u) {
    return 0.5f*u*(1.f + tanhf(0.7978845608028654f*(u + 0.044715f*u*u*u)));
}
__device__ __forceinline__ void ffma2(unsigned long long &d, unsigned long long a, unsigned long long b) {
    asm("fma.rn.f32x2 %0, %1, %2, %0;" : "+l"(d) : "l"(a), "l"(b));
}
__device__ __forceinline__ unsigned long long dup2(float a) {
    unsigned long long d;
    asm("mov.b64 %0, {%1, %1};" : "=l"(d) : "f"(a));
    return d;
}

__global__ void embed_init_kernel(const int* __restrict__ ids, const float* __restrict__ wte) {
    int idx = blockIdx.x * blockDim.x + threadIdx.x;
    if (idx >= BB*SS*DD) return;
    int r = idx / DD, d = idx - r*DD;
    g_embeds[idx] = wte[(size_t)ids[r]*DD + d];
}

__global__ void transpose_wte_kernel(const float* __restrict__ wte) {
    __shared__ float tile[32][33];
    int v0 = blockIdx.x * 32, d0 = blockIdx.y * 32;
    for (int i = threadIdx.y; i < 32; i += 8) {
        int v = v0 + i;
        tile[i][threadIdx.x] = (v < VV) ? wte[(size_t)v*DD + d0 + threadIdx.x] : 0.f;
    }
    __syncthreads();
    for (int i = threadIdx.y; i < 32; i += 8) {
        int d = d0 + i;
        int v = v0 + threadIdx.x;
        if (v < VPAD) g_wteT[(size_t)d*VPAD + v] = tile[threadIdx.x][i];
    }
}

__global__ void build_x_kernel(const int* __restrict__ pos_ids, const float* __restrict__ wpe,
                               int q_start, int qcount) {
    int idx = blockIdx.x * blockDim.x + threadIdx.x;
    int total = BB*qcount*DD;
    if (idx >= total) return;
    int r = idx / DD, d = idx - r*DD;
    int b = r / qcount, t = r - b*qcount;
    int s = q_start + t;
    int pos = pos_ids[b*SS + s];
    g_X[idx] = g_embeds[((size_t)b*SS + s)*DD + d] + wpe[(size_t)pos*DD + d];
}

__global__ void ln_kernel(const float* __restrict__ in, float* __restrict__ out,
                          const float* __restrict__ gam, const float* __restrict__ bet,
                          int qcount, int q_start, int scatter) {
    int r = blockIdx.x;
    const float* x = in + (size_t)r*DD;
    int tid = threadIdx.x;
    float x0 = x[tid], x1 = x[tid+256], x2 = x[tid+512];
    __shared__ float sh[8];
    float s = warpReduceSum(x0 + x1 + x2);
    if ((tid & 31) == 0) sh[tid >> 5] = s;
    __syncthreads();
    if (tid == 0) { float t = 0.f; for (int i = 0; i < 8; i++) t += sh[i]; sh[0] = t * (1.f/DD); }
    __syncthreads();
    float mean = sh[0];
    float d0 = x0 - mean, d1 = x1 - mean, d2 = x2 - mean;
    __syncthreads();
    float q = warpReduceSum(d0*d0 + d1*d1 + d2*d2);
    if ((tid & 31) == 0) sh[tid >> 5] = q;
    __syncthreads();
    if (tid == 0) { float t = 0.f; for (int i = 0; i < 8; i++) t += sh[i]; sh[0] = rsqrtf(t*(1.f/DD) + 1e-5f); }
    __syncthreads();
    float rstd = sh[0];
    int orow = r;
    if (scatter) { int b = r / qcount, t = r - b*qcount; orow = b*SS + q_start + t; }
    float* o = out + (size_t)orow*DD;
    o[tid]     = d0*rstd*gam[tid]     + bet[tid];
    o[tid+256] = d1*rstd*gam[tid+256] + bet[tid+256];
    o[tid+512] = d2*rstd*gam[tid+512] + bet[tid+512];
}

template<int ACT, int HASRES, int HASBIAS>
__global__ void __launch_bounds__(256, 2)
gemm128(const float* __restrict__ A, const float* __restrict__ W,
        const float* __restrict__ bias, const float* __restrict__ res,
        float* __restrict__ C, int M, int N, int K, int ldw, int ldc) {
    __shared__ float As[2][8][132];
    __shared__ float Bs[2][8][128];
    int tid = threadIdx.x;
    int row0 = blockIdx.y * 128, col0 = blockIdx.x * 128;
    int tx = tid & 15, ty = tid >> 4;

    unsigned long long acc[8][4];
    #pragma unroll
    for (int i = 0; i < 8; i++)
        #pragma unroll
        for (int j = 0; j < 4; j++) acc[i][j] = 0ULL;

    int Kc = K / gridDim.z;
    int kb = blockIdx.z * Kc;
    int KT = Kc >> 3;

    int arow = tid >> 1, acol = (tid & 1) * 4;
    int brow = tid >> 5, bcol = (tid & 31) * 4;
    bool avalid = (row0 + arow) < M;
    const float* aptr = A + (size_t)(row0 + arow)*K + kb + acol;
    const float* bptr = W + (size_t)(kb + brow)*ldw + col0 + bcol;

    float4 areg = avalid ? *(const float4*)aptr : make_float4(0.f,0.f,0.f,0.f);
    float4 breg = *(const float4*)bptr;
    As[0][acol+0][arow] = areg.x; As[0][acol+1][arow] = areg.y;
    As[0][acol+2][arow] = areg.z; As[0][acol+3][arow] = areg.w;
    *(float4*)&Bs[0][brow][bcol] = breg;
    __syncthreads();

    int buf = 0;
    for (int kt = 0; kt < KT; kt++) {
        if (kt + 1 < KT) {
            areg = avalid ? *(const float4*)(aptr + (kt + 1)*8) : make_float4(0.f,0.f,0.f,0.f);
            breg = *(const float4*)(bptr + (size_t)(kt + 1)*8*ldw);
        }
        #pragma unroll
        for (int k = 0; k < 8; k++) {
            ulonglong2 b01 = *(const ulonglong2*)&Bs[buf][k][tx*8];
            ulonglong2 b23 = *(const ulonglong2*)&Bs[buf][k][tx*8 + 4];
            float4 a0 = *(const float4*)&As[buf][k][ty*8];
            float4 a1 = *(const float4*)&As[buf][k][ty*8 + 4];
            float av[8] = {a0.x,a0.y,a0.z,a0.w,a1.x,a1.y,a1.z,a1.w};
            #pragma unroll
            for (int i = 0; i < 8; i++) {
                unsigned long long ad = dup2(av[i]);
                ffma2(acc[i][0], ad, b01.x);
                ffma2(acc[i][1], ad, b01.y);
                ffma2(acc[i][2], ad, b23.x);
                ffma2(acc[i][3], ad, b23.y);
            }
        }
        if (kt + 1 < KT) {
            int nb = buf ^ 1;
            As[nb][acol+0][arow] = areg.x; As[nb][acol+1][arow] = areg.y;
            As[nb][acol+2][arow] = areg.z; As[nb][acol+3][arow] = areg.w;
            *(float4*)&Bs[nb][brow][bcol] = breg;
        }
        __syncthreads();
        buf ^= 1;
    }

    if (gridDim.z > 1) {
        float* Cp = g_sk + (size_t)blockIdx.z * M * N;
        #pragma unroll
        for (int i = 0; i < 8; i++) {
            int gr = row0 + ty*8 + i;
            if (gr >= M) break;
            #pragma unroll
            for (int j = 0; j < 4; j++) {
                int gn = col0 + tx*8 + 2*j;
                if (gn < N)     Cp[(size_t)gr*N + gn]   = __uint_as_float((unsigned)(acc[i][j] & 0xffffffffULL));
                if (gn + 1 < N) Cp[(size_t)gr*N + gn+1] = __uint_as_float((unsigned)(acc[i][j] >> 32));
            }
        }
    } else {
        #pragma unroll
        for (int i = 0; i < 8; i++) {
            int gr = row0 + ty*8 + i;
            if (gr >= M) break;
            #pragma unroll
            for (int j = 0; j < 4; j++) {
                int gn = col0 + tx*8 + 2*j;
                float lo = __uint_as_float((unsigned)(acc[i][j] & 0xffffffffULL));
                float hi = __uint_as_float((unsigned)(acc[i][j] >> 32));
                if (gn < N) {
                    float v = lo;
                    if (HASBIAS) v += bias[gn];
                    if (ACT)     v = gelu_tanh(v);
                    if (HASRES)  v += res[(size_t)gr*ldc + gn];
                    C[(size_t)gr*ldc + gn] = v;
                }
                if (gn + 1 < N) {
                    float v = hi;
                    if (HASBIAS) v += bias[gn+1];
                    if (ACT)     v = gelu_tanh(v);
                    if (HASRES)  v += res[(size_t)gr*ldc + gn+1];
                    C[(size_t)gr*ldc + gn+1] = v;
                }
            }
        }
    }
}

template<int ACT, int HASRES>
__global__ void gemmred(const float* __restrict__ bias, const float* __restrict__ res,
                        float* __restrict__ C, int M, int N, int splits) {
    int idx = blockIdx.x * 256 + threadIdx.x;
    if (idx >= M*N) return;
    int n = idx % N;
    float s = bias[n];
    for (int z = 0; z < splits; z++) s += g_sk[(size_t)z*M*N + idx];
    if (ACT)    s = gelu_tanh(s);
    if (HASRES) s += res[idx];
    C[idx] = s;
}

__global__ void gemv4_part(const float* __restrict__ A, const float* __restrict__ W, int N, int K) {
    __shared__ float Ash[4][128];
    int tid = threadIdx.x;
    int k0 = blockIdx.y * 128;
    for (int i = tid; i < 512; i += 128) {
        int r = i >> 7, k = i & 127;
        Ash[r][k] = A[(size_t)r*K + k0 + k];
    }
    __syncthreads();
    int n = blockIdx.x * 128 + tid;
    const float* wp = W + (size_t)k0*N + n;
    float s0=0.f, s1=0.f, s2=0.f, s3=0.f;
    #pragma unroll 8
    for (int k = 0; k < 128; k++) {
        float w = wp[(size_t)k*N];
        s0 = fmaf(w, Ash[0][k], s0);
        s1 = fmaf(w, Ash[1][k], s1);
        s2 = fmaf(w, Ash[2][k], s2);
        s3 = fmaf(w, Ash[3][k], s3);
    }
    float* pp = g_part + (size_t)blockIdx.y*4*DFFN + n;
    pp[0] = s0; pp[DFFN] = s1; pp[2*DFFN] = s2; pp[3*DFFN] = s3;
}

template<int ACT, int HASRES>
__global__ void gemv4_red(const float* __restrict__ bias, const float* __restrict__ res,
                          float* __restrict__ C, int N, int kchunks) {
    int n = blockIdx.x * 256 + threadIdx.x;
    if (n >= N) return;
    #pragma unroll
    for (int r = 0; r < 4; r++) {
        float s = bias[n];
        for (int c = 0; c < kchunks; c++) s += g_part[(size_t)c*4*DFFN + r*DFFN + n];
        if (ACT)    s = gelu_tanh(s);
        if (HASRES) s += res[(size_t)r*N + n];
        C[(size_t)r*N + n] = s;
    }
}

__global__ void kv_scatter(int l, int q_start, int qcount) {
    int idx = blockIdx.x * 256 + threadIdx.x;
    int total = BB*qcount*DD;
    if (idx >= total) return;
    int r = idx / DD, d = idx - r*DD;
    int b = r / qcount, t = r - b*qcount;
    int pos = q_start + t;
    int h = d >> 6, dh = d & 63;
    size_t cidx = ((size_t)((l*BB + b)*HH + h)*SS + pos)*DHH + dh;
    g_K[cidx] = g_QKV[(size_t)r*(3*DD) + DD   + d];
    g_V[cidx] = g_QKV[(size_t)r*(3*DD) + 2*DD + d];
}

__global__ void attn_kernel(int l, int q_start, int qcount, const int* __restrict__ amask) {
    __shared__ float qsh[8][4][64];
    int w = threadIdx.x >> 5, lane = threadIdx.x & 31;
    int nqt = (qcount + 3) >> 2;
    int gw = blockIdx.x * 8 + w;
    int total = nqt * BB * HH;
    if (gw >= total) return;
    int h = gw % HH; int r1 = gw / HH; int b = r1 % BB; int qt = r1 / BB;
    int t0 = qt * 4;

    #pragma unroll
    for (int i = 0; i < 4; i++) {
        int t = t0 + i; if (t >= qcount) t = qcount - 1;
        const float* qp = g_QKV + (size_t)(b*qcount + t)*(3*DD) + h*DHH;
        qsh[w][i][lane]      = qp[lane]      * ATT_SCALE;
        qsh[w][i][lane + 32] = qp[lane + 32] * ATT_SCALE;
    }
    __syncwarp();

    int qlast = min(t0 + 3, qcount - 1);
    int qmaxpos = q_start + qlast;
    const float* kc = g_K + (size_t)((l*BB + b)*HH + h)*SS*DHH;
    const float* vc = g_V + (size_t)((l*BB + b)*HH + h)*SS*DHH;

    float m0=-1e30f, m1=-1e30f, m2=-1e30f, m3=-1e30f;
    float den0=0.f, den1=0.f, den2=0.f, den3=0.f;
    float2 ac0={0.f,0.f}, ac1={0.f,0.f}, ac2={0.f,0.f}, ac3={0.f,0.f};

    for (int j0 = 0; j0 <= qmaxpos; j0 += 32) {
        int j = j0 + lane;
        float s0=-1e30f, s1=-1e30f, s2=-1e30f, s3=-1e30f;
        if (j <= qmaxpos && amask[b*SS + j] != 0) {
            const float4* kr = (const float4*)(kc + (size_t)j*DHH);
            float u0=0.f, u1=0.f, u2=0.f, u3=0.f;
            #pragma unroll
            for (int i2 = 0; i2 < 16; i2++) {
                float4 kv = kr[i2];
                float4 q0v = *(const float4*)&qsh[w][0][i2*4];
                float4 q1v = *(const float4*)&qsh[w][1][i2*4];
                float4 q2v = *(const float4*)&qsh[w][2][i2*4];
                float4 q3v = *(const float4*)&qsh[w][3][i2*4];
                u0 += kv.x*q0v.x + kv.y*q0v.y + kv.z*q0v.z + kv.w*q0v.w;
                u1 += kv.x*q1v.x + kv.y*q1v.y + kv.z*q1v.z + kv.w*q1v.w;
                u2 += kv.x*q2v.x + kv.y*q2v.y + kv.z*q2v.z + kv.w*q2v.w;
                u3 += kv.x*q3v.x + kv.y*q3v.y + kv.z*q3v.z + kv.w*q3v.w;
            }
            s0 = (j <= q_start + t0    ) ? u0 : -1e30f;
            s1 = (j <= q_start + t0 + 1) ? u1 : -1e30f;
            s2 = (j <= q_start + t0 + 2) ? u2 : -1e30f;
            s3 = (j <= q_start + t0 + 3) ? u3 : -1e30f;
        }
        float nm0 = fmaxf(m0, warpReduceMax(s0));
        float nm1 = fmaxf(m1, warpReduceMax(s1));
        float nm2 = fmaxf(m2, warpReduceMax(s2));
        float nm3 = fmaxf(m3, warpReduceMax(s3));
        float p0 = __expf(s0 - nm0), p1 = __expf(s1 - nm1);
        float p2 = __expf(s2 - nm2), p3 = __expf(s3 - nm3);
        float ps0 = warpReduceSum(p0), ps1 = warpReduceSum(p1);
        float ps2 = warpReduceSum(p2), ps3 = warpReduceSum(p3);
        float al0 = __expf(m0 - nm0), al1 = __expf(m1 - nm1);
        float al2 = __expf(m2 - nm2), al3 = __expf(m3 - nm3);
        den0 = den0*al0 + ps0; ac0.x *= al0; ac0.y *= al0; m0 = nm0;
        den1 = den1*al1 + ps1; ac1.x *= al1; ac1.y *= al1; m1 = nm1;
        den2 = den2*al2 + ps2; ac2.x *= al2; ac2.y *= al2; m2 = nm2;
        den3 = den3*al3 + ps3; ac3.x *= al3; ac3.y *= al3; m3 = nm3;

        int jcnt = min(32, qmaxpos - j0 + 1);
        for (int jj = 0; jj < jcnt; jj++) {
            float2 vv = *(const float2*)(vc + (size_t)(j0 + jj)*DHH + lane*2);
            float q0p = __shfl_sync(0xffffffffu, p0, jj);
            float q1p = __shfl_sync(0xffffffffu, p1, jj);
            float q2p = __shfl_sync(0xffffffffu, p2, jj);
            float q3p = __shfl_sync(0xffffffffu, p3, jj);
            ac0.x = fmaf(q0p, vv.x, ac0.x); ac0.y = fmaf(q0p, vv.y, ac0.y);
            ac1.x = fmaf(q1p, vv.x, ac1.x); ac1.y = fmaf(q1p, vv.y, ac1.y);
            ac2.x = fmaf(q2p, vv.x, ac2.x); ac2.y = fmaf(q2p, vv.y, ac2.y);
            ac3.x = fmaf(q3p, vv.x, ac3.x); ac3.y = fmaf(q3p, vv.y, ac3.y);
        }
    }
    float2 accs[4] = {ac0, ac1, ac2, ac3};
    float dens[4] = {den0, den1, den2, den3};
    #pragma unroll
    for (int i = 0; i < 4; i++) {
        int t = t0 + i;
        if (t < qcount) {
            float inv = 1.f / dens[i];
            float2 o = make_float2(accs[i].x*inv, accs[i].y*inv);
            *(float2*)&g_CTX[(size_t)(b*qcount + t)*DD + h*DHH + lane*2] = o;
        }
    }
}

__global__ void latent_update_kernel(int slot) {
    int idx = blockIdx.x * blockDim.x + threadIdx.x;
    if (idx >= BB*DD) return;
    int b = idx / DD, d = idx - b*DD;
    g_embeds[((size_t)b*SS + slot)*DD + d] = g_HID[((size_t)b*SS + (slot - 1))*DD + d];
}

__global__ void loss_row_kernel(const float* __restrict__ logits, const int* __restrict__ labels) {
    int r = blockIdx.x;
    int b = r / (SS-1), t = r - b*(SS-1);
    const float* x = logits + ((size_t)(b*SS + t))*VV;
    int tid = threadIdx.x;
    __shared__ float sh[8];
    float mx = -1e30f;
    for (int i = tid; i < VV; i += 256) mx = fmaxf(mx, x[i]);
    mx = warpReduceMax(mx);
    if ((tid & 31) == 0) sh[tid >> 5] = mx;
    __syncthreads();
    if (tid == 0) { float m = sh[0]; for (int i = 1; i < 8; i++) m = fmaxf(m, sh[i]); sh[0] = m; }
    __syncthreads();
    mx = sh[0];
    __syncthreads();
    float se = 0.f;
    for (int i = tid; i < VV; i += 256) se += __expf(x[i] - mx);
    se = warpReduceSum(se);
    if ((tid & 31) == 0) sh[tid >> 5] = se;
    __syncthreads();
    if (tid == 0) {
        float s = 0.f; for (int i = 0; i < 8; i++) s += sh[i];
        int lab = labels[b*SS + t + 1];
        g_nll[r] = logf(s) + mx - x[lab];
    }
}
__global__ void loss_final_kernel(float* out) {
    int tid = threadIdx.x;
    const int NR = BB*(SS-1);
    __shared__ float sh[8];
    float s = 0.f;
    for (int i = tid; i < NR; i += 256) s += g_nll[i];
    s = warpReduceSum(s);
    if ((tid & 31) == 0) sh[tid >> 5] = s;
    __syncthreads();
    if (tid == 0) {
        float t = 0.f; for (int i = 0; i < 8; i++) t += sh[i];
        out[0] = t / (float)NR;
    }
}

static int pick_z(int nx, int ny) {
    int z = 1;
    while (z < 8 && nx*ny*z < 148) z *= 2;
    return z;
}

extern "C" void kernel_launch(void* const* d_in, const int* in_sizes, int n_in,
                              void* d_out, int out_size) {
    const int*   input_ids = (const int*)d_in[0];
    const int*   amask     = (const int*)d_in[1];
    const int*   labels    = (const int*)d_in[2];
    const int*   pos_ids   = (const int*)d_in[3];
    const float* wte   = (const float*)d_in[4];
    const float* wpe   = (const float*)d_in[5];
    const float* ln1_g = (const float*)d_in[6];
    const float* ln1_b = (const float*)d_in[7];
    const float* Wqkv  = (const float*)d_in[8];
    const float* bqkv  = (const float*)d_in[9];
    const float* Wo    = (const float*)d_in[10];
    const float* bo    = (const float*)d_in[11];
    const float* ln2_g = (const float*)d_in[12];
    const float* ln2_b = (const float*)d_in[13];
    const float* W1    = (const float*)d_in[14];
    const float* b1    = (const float*)d_in[15];
    const float* W2    = (const float*)d_in[16];
    const float* b2    = (const float*)d_in[17];
    const float* lnf_g = (const float*)d_in[18];
    const float* lnf_b = (const float*)d_in[19];

    float* out    = (float*)d_out;
    float* logits = out + 1;

    float *pX, *pH, *pHID, *pQKV, *pCTX, *pG, *pWT;
    cudaGetSymbolAddress((void**)&pX,   g_X);
    cudaGetSymbolAddress((void**)&pH,   g_H);
    cudaGetSymbolAddress((void**)&pHID, g_HID);
    cudaGetSymbolAddress((void**)&pQKV, g_QKV);
    cudaGetSymbolAddress((void**)&pCTX, g_CTX);
    cudaGetSymbolAddress((void**)&pG,   g_G);
    cudaGetSymbolAddress((void**)&pWT,  g_wteT);

    embed_init_kernel<<<(BB*SS*DD + 255)/256, 256>>>(input_ids, wte);
    transpose_wte_kernel<<<dim3(VPAD/32, DD/32), dim3(32, 8)>>>(wte);

    const int QS[7] = {0, 64, 65, 66, 67, 68, 69};
    const int QC[7] = {64, 1,  1,  1,  1,  1,  SS - 69};

    for (int p = 0; p < 7; p++) {
        int qs = QS[p], qc = QC[p];
        int M = BB * qc;

        build_x_kernel<<<(M*DD + 255)/256, 256>>>(pos_ids, wpe, qs, qc);

        for (int l = 0; l < NLAYER; l++) {
            const float* Wq  = Wqkv + (size_t)l*DD*3*DD;  const float* bq  = bqkv + (size_t)l*3*DD;
            const float* Wol = Wo   + (size_t)l*DD*DD;    const float* bol = bo   + (size_t)l*DD;
            const float* W1l = W1   + (size_t)l*DD*DFFN;  const float* b1l = b1   + (size_t)l*DFFN;
            const float* W2l = W2   + (size_t)l*DFFN*DD;  const float* b2l = b2   + (size_t)l*DD;

            ln_kernel<<<M, 256>>>(pX, pH, ln1_g + l*DD, ln1_b + l*DD, qc, qs, 0);

            if (qc == 1) {
                gemv4_part<<<dim3(3*DD/128, DD/128), 128>>>(pH, Wq, 3*DD, DD);
                gemv4_red<0,0><<<(3*DD + 255)/256, 256>>>(bq, 0, pQKV, 3*DD, DD/128);
            } else {
                int ny = (M + 127)/128;
                int z = pick_z(18, ny);
                if (z == 1) {
                    gemm128<0,0,1><<<dim3(18, ny), 256>>>(pH, Wq, bq, 0, pQKV, M, 3*DD, DD, 3*DD, 3*DD);
                } else {
                    gemm128<0,0,0><<<dim3(18, ny, z), 256>>>(pH, Wq, 0, 0, pQKV, M, 3*DD, DD, 3*DD, 3*DD);
                    gemmred<0,0><<<(M*3*DD + 255)/256, 256>>>(bq, 0, pQKV, M, 3*DD, z);
                }
            }

            kv_scatter<<<(M*DD + 255)/256, 256>>>(l, qs, qc);

            int nqt = (qc + 3)/4;
            attn_kernel<<<(nqt*BB*HH + 7)/8, 256>>>(l, qs, qc, amask);

            if (qc == 1) {
                gemv4_part<<<dim3(DD/128, DD/128), 128>>>(pCTX, Wol, DD, DD);
                gemv4_red<0,1><<<(DD + 255)/256, 256>>>(bol, pX, pX, DD, DD/128);
            } else {
                int ny = (M + 127)/128;
                int z = pick_z(6, ny);
                if (z == 1) {
                    gemm128<0,1,1><<<dim3(6, ny), 256>>>(pCTX, Wol, bol, pX, pX, M, DD, DD, DD, DD);
                } else {
                    gemm128<0,0,0><<<dim3(6, ny, z), 256>>>(pCTX, Wol, 0, 0, pX, M, DD, DD, DD, DD);
                    gemmred<0,1><<<(M*DD + 255)/256, 256>>>(bol, pX, pX, M, DD, z);
                }
            }

            ln_kernel<<<M, 256>>>(pX, pH, ln2_g + l*DD, ln2_b + l*DD, qc, qs, 0);

            if (qc == 1) {
                gemv4_part<<<dim3(DFFN/128, DD/128), 128>>>(pH, W1l, DFFN, DD);
                gemv4_red<1,0><<<(DFFN + 255)/256, 256>>>(b1l, 0, pG, DFFN, DD/128);
                gemv4_part<<<dim3(DD/128, DFFN/128), 128>>>(pG, W2l, DD, DFFN);
                gemv4_red<0,1><<<(DD + 255)/256, 256>>>(b2l, pX, pX, DD, DFFN/128);
            } else {
                int ny = (M + 127)/128;
                int z1 = pick_z(24, ny);
                if (z1 == 1) {
                    gemm128<1,0,1><<<dim3(24, ny), 256>>>(pH, W1l, b1l, 0, pG, M, DFFN, DD, DFFN, DFFN);
                } else {
                    gemm128<0,0,0><<<dim3(24, ny, z1), 256>>>(pH, W1l, 0, 0, pG, M, DFFN, DD, DFFN, DFFN);
                    gemmred<1,0><<<(M*DFFN + 255)/256, 256>>>(b1l, 0, pG, M, DFFN, z1);
                }
                int z2 = pick_z(6, ny);
                if (z2 == 1) {
                    gemm128<0,1,1><<<dim3(6, ny), 256>>>(pG, W2l, b2l, pX, pX, M, DD, DFFN, DD, DD);
                } else {
                    gemm128<0,0,0><<<dim3(6, ny, z2), 256>>>(pG, W2l, 0, 0, pX, M, DD, DFFN, DD, DD);
                    gemmred<0,1><<<(M*DD + 255)/256, 256>>>(b2l, pX, pX, M, DD, z2);
                }
            }
        }

        ln_kernel<<<M, 256>>>(pX, pHID, lnf_g, lnf_b, qc, qs, 1);

        if (p < NLAT) {
            latent_update_kernel<<<(BB*DD + 255)/256, 256>>>(LAT_START + p);
        }
    }

    gemm128<0,0,0><<<dim3(VPAD/128, (BB*SS)/128), 256>>>(pHID, pWT, 0, 0, logits,
                                                          BB*SS, VV, DD, VPAD, VV);

    loss_row_kernel<<<BB*(SS-1), 256>>>(logits, labels);
    loss_final_kernel<<<1, 256>>>(out);
}

// round 11
// speedup vs baseline: 1.9415x; 1.0042x over previous
#include <cuda_runtime.h>
#include <math.h>

#define BB   4
#define SS   512
#define VV   50257
#define VPAD 50304
#define DD   768
#define HH   12
#define DHH  64
#define NLAYER 2
#define DFFN 3072
#define LAT_START 64
#define NLAT 6
#define ATT_SCALE 0.125f

// ---- scratch (device globals; zero-init; no allocations) ----
static __device__ float g_embeds[BB*SS*DD];
static __device__ float g_X   [BB*SS*DD];
static __device__ float g_H   [BB*SS*DD];
static __device__ float g_HID [BB*SS*DD];
static __device__ float g_QKV [BB*SS*3*DD];
static __device__ float g_CTX [BB*SS*DD];
static __device__ float g_G   [BB*SS*DFFN];
static __device__ float g_K   [NLAYER*BB*HH*SS*DHH];
static __device__ float g_V   [NLAYER*BB*HH*SS*DHH];
static __device__ float g_wteT[DD*VPAD];
static __device__ float g_part[24*4*DFFN];
static __device__ float g_sk  [8*1024*1024];
static __device__ float g_nll [BB*(SS-1)];

__device__ __forceinline__ float warpReduceSum(float v) {
    #pragma unroll
    for (int o = 16; o; o >>= 1) v += __shfl_xor_sync(0xffffffffu, v, o);
    return v;
}
__device__ __forceinline__ float warpReduceMax(float v) {
    #pragma unroll
    for (int o = 16; o; o >>= 1) v = fmaxf(v, __shfl_xor_sync(0xffffffffu, v, o));
    return v;
}
__device__ __forceinline__ float gelu_tanh(float u) {
    return 0.5f*u*(1.f + tanhf(0.7978845608028654f*(u + 0.044715f*u*u*u)));
}
__device__ __forceinline__ void ffma2(unsigned long long &d, unsigned long long a, unsigned long long b) {
    asm("fma.rn.f32x2 %0, %1, %2, %0;" : "+l"(d) : "l"(a), "l"(b));
}
__device__ __forceinline__ unsigned long long dup2(float a) {
    unsigned long long d;
    asm("mov.b64 %0, {%1, %1};" : "=l"(d) : "f"(a));
    return d;
}

__global__ void embed_init_kernel(const int* __restrict__ ids, const float* __restrict__ wte) {
    int idx = blockIdx.x * blockDim.x + threadIdx.x;
    if (idx >= BB*SS*DD) return;
    int r = idx / DD, d = idx - r*DD;
    g_embeds[idx] = wte[(size_t)ids[r]*DD + d];
}

__global__ void transpose_wte_kernel(const float* __restrict__ wte) {
    __shared__ float tile[32][33];
    int v0 = blockIdx.x * 32, d0 = blockIdx.y * 32;
    for (int i = threadIdx.y; i < 32; i += 8) {
        int v = v0 + i;
        tile[i][threadIdx.x] = (v < VV) ? wte[(size_t)v*DD + d0 + threadIdx.x] : 0.f;
    }
    __syncthreads();
    for (int i = threadIdx.y; i < 32; i += 8) {
        int d = d0 + i;
        int v = v0 + threadIdx.x;
        if (v < VPAD) g_wteT[(size_t)d*VPAD + v] = tile[threadIdx.x][i];
    }
}

__global__ void build_x_kernel(const int* __restrict__ pos_ids, const float* __restrict__ wpe,
                               int q_start, int qcount) {
    int idx = blockIdx.x * blockDim.x + threadIdx.x;
    int total = BB*qcount*DD;
    if (idx >= total) return;
    int r = idx / DD, d = idx - r*DD;
    int b = r / qcount, t = r - b*qcount;
    int s = q_start + t;
    int pos = pos_ids[b*SS + s];
    g_X[idx] = g_embeds[((size_t)b*SS + s)*DD + d] + wpe[(size_t)pos*DD + d];
}

__global__ void ln_kernel(const float* __restrict__ in, float* __restrict__ out,
                          const float* __restrict__ gam, const float* __restrict__ bet,
                          int qcount, int q_start, int scatter) {
    int r = blockIdx.x;
    const float* x = in + (size_t)r*DD;
    int tid = threadIdx.x;
    float x0 = x[tid], x1 = x[tid+256], x2 = x[tid+512];
    __shared__ float sh[8];
    float s = warpReduceSum(x0 + x1 + x2);
    if ((tid & 31) == 0) sh[tid >> 5] = s;
    __syncthreads();
    if (tid == 0) { float t = 0.f; for (int i = 0; i < 8; i++) t += sh[i]; sh[0] = t * (1.f/DD); }
    __syncthreads();
    float mean = sh[0];
    float d0 = x0 - mean, d1 = x1 - mean, d2 = x2 - mean;
    __syncthreads();
    float q = warpReduceSum(d0*d0 + d1*d1 + d2*d2);
    if ((tid & 31) == 0) sh[tid >> 5] = q;
    __syncthreads();
    if (tid == 0) { float t = 0.f; for (int i = 0; i < 8; i++) t += sh[i]; sh[0] = rsqrtf(t*(1.f/DD) + 1e-5f); }
    __syncthreads();
    float rstd = sh[0];
    int orow = r;
    if (scatter) { int b = r / qcount, t = r - b*qcount; orow = b*SS + q_start + t; }
    float* o = out + (size_t)orow*DD;
    o[tid]     = d0*rstd*gam[tid]     + bet[tid];
    o[tid+256] = d1*rstd*gam[tid+256] + bet[tid+256];
    o[tid+512] = d2*rstd*gam[tid+512] + bet[tid+512];
}

template<int ACT, int HASRES, int HASBIAS>
__global__ void __launch_bounds__(256, 2)
gemm128(const float* __restrict__ A, const float* __restrict__ W,
        const float* __restrict__ bias, const float* __restrict__ res,
        float* __restrict__ C, int M, int N, int K, int ldw, int ldc) {
    __shared__ float As[2][8][132];
    __shared__ float Bs[2][8][128];
    int tid = threadIdx.x;
    int row0 = blockIdx.y * 128, col0 = blockIdx.x * 128;
    int tx = tid & 15, ty = tid >> 4;

    unsigned long long acc[8][4];
    #pragma unroll
    for (int i = 0; i < 8; i++)
        #pragma unroll
        for (int j = 0; j < 4; j++) acc[i][j] = 0ULL;

    int Kc = K / gridDim.z;
    int kb = blockIdx.z * Kc;
    int KT = Kc >> 3;

    int arow = tid >> 1, acol = (tid & 1) * 4;
    int brow = tid >> 5, bcol = (tid & 31) * 4;
    bool avalid = (row0 + arow) < M;
    const float* aptr = A + (size_t)(row0 + arow)*K + kb + acol;
    const float* bptr = W + (size_t)(kb + brow)*ldw + col0 + bcol;

    float4 areg = avalid ? *(const float4*)aptr : make_float4(0.f,0.f,0.f,0.f);
    float4 breg = *(const float4*)bptr;
    As[0][acol+0][arow] = areg.x; As[0][acol+1][arow] = areg.y;
    As[0][acol+2][arow] = areg.z; As[0][acol+3][arow] = areg.w;
    *(float4*)&Bs[0][brow][bcol] = breg;
    __syncthreads();

    int buf = 0;
    for (int kt = 0; kt < KT; kt++) {
        if (kt + 1 < KT) {
            areg = avalid ? *(const float4*)(aptr + (kt + 1)*8) : make_float4(0.f,0.f,0.f,0.f);
            breg = *(const float4*)(bptr + (size_t)(kt + 1)*8*ldw);
        }
        #pragma unroll
        for (int k = 0; k < 8; k++) {
            ulonglong2 b01 = *(const ulonglong2*)&Bs[buf][k][tx*8];
            ulonglong2 b23 = *(const ulonglong2*)&Bs[buf][k][tx*8 + 4];
            float4 a0 = *(const float4*)&As[buf][k][ty*8];
            float4 a1 = *(const float4*)&As[buf][k][ty*8 + 4];
            float av[8] = {a0.x,a0.y,a0.z,a0.w,a1.x,a1.y,a1.z,a1.w};
            #pragma unroll
            for (int i = 0; i < 8; i++) {
                unsigned long long ad = dup2(av[i]);
                ffma2(acc[i][0], ad, b01.x);
                ffma2(acc[i][1], ad, b01.y);
                ffma2(acc[i][2], ad, b23.x);
                ffma2(acc[i][3], ad, b23.y);
            }
        }
        if (kt + 1 < KT) {
            int nb = buf ^ 1;
            As[nb][acol+0][arow] = areg.x; As[nb][acol+1][arow] = areg.y;
            As[nb][acol+2][arow] = areg.z; As[nb][acol+3][arow] = areg.w;
            *(float4*)&Bs[nb][brow][bcol] = breg;
        }
        __syncthreads();
        buf ^= 1;
    }

    if (gridDim.z > 1) {
        float* Cp = g_sk + (size_t)blockIdx.z * M * N;
        #pragma unroll
        for (int i = 0; i < 8; i++) {
            int gr = row0 + ty*8 + i;
            if (gr >= M) break;
            #pragma unroll
            for (int j = 0; j < 4; j++) {
                int gn = col0 + tx*8 + 2*j;
                if (gn < N)     Cp[(size_t)gr*N + gn]   = __uint_as_float((unsigned)(acc[i][j] & 0xffffffffULL));
                if (gn + 1 < N) Cp[(size_t)gr*N + gn+1] = __uint_as_float((unsigned)(acc[i][j] >> 32));
            }
        }
    } else {
        #pragma unroll
        for (int i = 0; i < 8; i++) {
            int gr = row0 + ty*8 + i;
            if (gr >= M) break;
            #pragma unroll
            for (int j = 0; j < 4; j++) {
                int gn = col0 + tx*8 + 2*j;
                float lo = __uint_as_float((unsigned)(acc[i][j] & 0xffffffffULL));
                float hi = __uint_as_float((unsigned)(acc[i][j] >> 32));
                if (gn < N) {
                    float v = lo;
                    if (HASBIAS) v += bias[gn];
                    if (ACT)     v = gelu_tanh(v);
                    if (HASRES)  v += res[(size_t)gr*ldc + gn];
                    C[(size_t)gr*ldc + gn] = v;
                }
                if (gn + 1 < N) {
                    float v = hi;
                    if (HASBIAS) v += bias[gn+1];
                    if (ACT)     v = gelu_tanh(v);
                    if (HASRES)  v += res[(size_t)gr*ldc + gn+1];
                    C[(size_t)gr*ldc + gn+1] = v;
                }
            }
        }
    }
}

template<int ACT, int HASRES>
__global__ void gemmred(const float* __restrict__ bias, const float* __restrict__ res,
                        float* __restrict__ C, int M, int N, int splits) {
    int idx = blockIdx.x * 256 + threadIdx.x;
    if (idx >= M*N) return;
    int n = idx % N;
    float s = bias[n];
    for (int z = 0; z < splits; z++) s += g_sk[(size_t)z*M*N + idx];
    if (ACT)    s = gelu_tanh(s);
    if (HASRES) s += res[idx];
    C[idx] = s;
}

__global__ void gemv4_part(const float* __restrict__ A, const float* __restrict__ W, int N, int K) {
    __shared__ float Ash[4][128];
    int tid = threadIdx.x;
    int k0 = blockIdx.y * 128;
    for (int i = tid; i < 512; i += 128) {
        int r = i >> 7, k = i & 127;
        Ash[r][k] = A[(size_t)r*K + k0 + k];
    }
    __syncthreads();
    int n = blockIdx.x * 128 + tid;
    const float* wp = W + (size_t)k0*N + n;
    float s0=0.f, s1=0.f, s2=0.f, s3=0.f;
    #pragma unroll 8
    for (int k = 0; k < 128; k++) {
        float w = wp[(size_t)k*N];
        s0 = fmaf(w, Ash[0][k], s0);
        s1 = fmaf(w, Ash[1][k], s1);
        s2 = fmaf(w, Ash[2][k], s2);
        s3 = fmaf(w, Ash[3][k], s3);
    }
    float* pp = g_part + (size_t)blockIdx.y*4*DFFN + n;
    pp[0] = s0; pp[DFFN] = s1; pp[2*DFFN] = s2; pp[3*DFFN] = s3;
}

template<int ACT, int HASRES>
__global__ void gemv4_red(const float* __restrict__ bias, const float* __restrict__ res,
                          float* __restrict__ C, int N, int kchunks) {
    int n = blockIdx.x * 256 + threadIdx.x;
    if (n >= N) return;
    #pragma unroll
    for (int r = 0; r < 4; r++) {
        float s = bias[n];
        for (int c = 0; c < kchunks; c++) s += g_part[(size_t)c*4*DFFN + r*DFFN + n];
        if (ACT)    s = gelu_tanh(s);
        if (HASRES) s += res[(size_t)r*N + n];
        C[(size_t)r*N + n] = s;
    }
}

__global__ void kv_scatter(int l, int q_start, int qcount) {
    int idx = blockIdx.x * 256 + threadIdx.x;
    int total = BB*qcount*DD;
    if (idx >= total) return;
    int r = idx / DD, d = idx - r*DD;
    int b = r / qcount, t = r - b*qcount;
    int pos = q_start + t;
    int h = d >> 6, dh = d & 63;
    size_t cidx = ((size_t)((l*BB + b)*HH + h)*SS + pos)*DHH + dh;
    g_K[cidx] = g_QKV[(size_t)r*(3*DD) + DD   + d];
    g_V[cidx] = g_QKV[(size_t)r*(3*DD) + 2*DD + d];
}

__global__ void attn_kernel(int l, int q_start, int qcount, const int* __restrict__ amask) {
    __shared__ float qsh[8][4][64];
    int w = threadIdx.x >> 5, lane = threadIdx.x & 31;
    int nqt = (qcount + 3) >> 2;
    int gw = blockIdx.x * 8 + w;
    int total = nqt * BB * HH;
    if (gw >= total) return;
    int h = gw % HH; int r1 = gw / HH; int b = r1 % BB; int qt = r1 / BB;
    int t0 = qt * 4;

    #pragma unroll
    for (int i = 0; i < 4; i++) {
        int t = t0 + i; if (t >= qcount) t = qcount - 1;
        const float* qp = g_QKV + (size_t)(b*qcount + t)*(3*DD) + h*DHH;
        qsh[w][i][lane]      = qp[lane]      * ATT_SCALE;
        qsh[w][i][lane + 32] = qp[lane + 32] * ATT_SCALE;
    }
    __syncwarp();

    int qlast = min(t0 + 3, qcount - 1);
    int qmaxpos = q_start + qlast;
    const float* kc = g_K + (size_t)((l*BB + b)*HH + h)*SS*DHH;
    const float* vc = g_V + (size_t)((l*BB + b)*HH + h)*SS*DHH;

    float m0=-1e30f, m1=-1e30f, m2=-1e30f, m3=-1e30f;
    float den0=0.f, den1=0.f, den2=0.f, den3=0.f;
    float2 ac0={0.f,0.f}, ac1={0.f,0.f}, ac2={0.f,0.f}, ac3={0.f,0.f};

    for (int j0 = 0; j0 <= qmaxpos; j0 += 32) {
        int j = j0 + lane;
        float s0=-1e30f, s1=-1e30f, s2=-1e30f, s3=-1e30f;
        if (j <= qmaxpos && amask[b*SS + j] != 0) {
            const float4* kr = (const float4*)(kc + (size_t)j*DHH);
            float u0=0.f, u1=0.f, u2=0.f, u3=0.f;
            #pragma unroll
            for (int i2 = 0; i2 < 16; i2++) {
                float4 kv = kr[i2];
                float4 q0v = *(const float4*)&qsh[w][0][i2*4];
                float4 q1v = *(const float4*)&qsh[w][1][i2*4];
                float4 q2v = *(const float4*)&qsh[w][2][i2*4];
                float4 q3v = *(const float4*)&qsh[w][3][i2*4];
                u0 += kv.x*q0v.x + kv.y*q0v.y + kv.z*q0v.z + kv.w*q0v.w;
                u1 += kv.x*q1v.x + kv.y*q1v.y + kv.z*q1v.z + kv.w*q1v.w;
                u2 += kv.x*q2v.x + kv.y*q2v.y + kv.z*q2v.z + kv.w*q2v.w;
                u3 += kv.x*q3v.x + kv.y*q3v.y + kv.z*q3v.z + kv.w*q3v.w;
            }
            s0 = (j <= q_start + t0    ) ? u0 : -1e30f;
            s1 = (j <= q_start + t0 + 1) ? u1 : -1e30f;
            s2 = (j <= q_start + t0 + 2) ? u2 : -1e30f;
            s3 = (j <= q_start + t0 + 3) ? u3 : -1e30f;
        }
        float nm0 = fmaxf(m0, warpReduceMax(s0));
        float nm1 = fmaxf(m1, warpReduceMax(s1));
        float nm2 = fmaxf(m2, warpReduceMax(s2));
        float nm3 = fmaxf(m3, warpReduceMax(s3));
        float p0 = __expf(s0 - nm0), p1 = __expf(s1 - nm1);
        float p2 = __expf(s2 - nm2), p3 = __expf(s3 - nm3);
        float ps0 = warpReduceSum(p0), ps1 = warpReduceSum(p1);
        float ps2 = warpReduceSum(p2), ps3 = warpReduceSum(p3);
        float al0 = __expf(m0 - nm0), al1 = __expf(m1 - nm1);
        float al2 = __expf(m2 - nm2), al3 = __expf(m3 - nm3);
        den0 = den0*al0 + ps0; ac0.x *= al0; ac0.y *= al0; m0 = nm0;
        den1 = den1*al1 + ps1; ac1.x *= al1; ac1.y *= al1; m1 = nm1;
        den2 = den2*al2 + ps2; ac2.x *= al2; ac2.y *= al2; m2 = nm2;
        den3 = den3*al3 + ps3; ac3.x *= al3; ac3.y *= al3; m3 = nm3;

        int jcnt = min(32, qmaxpos - j0 + 1);
        for (int jj = 0; jj < jcnt; jj++) {
            float2 vv = *(const float2*)(vc + (size_t)(j0 + jj)*DHH + lane*2);
            float q0p = __shfl_sync(0xffffffffu, p0, jj);
            float q1p = __shfl_sync(0xffffffffu, p1, jj);
            float q2p = __shfl_sync(0xffffffffu, p2, jj);
            float q3p = __shfl_sync(0xffffffffu, p3, jj);
            ac0.x = fmaf(q0p, vv.x, ac0.x); ac0.y = fmaf(q0p, vv.y, ac0.y);
            ac1.x = fmaf(q1p, vv.x, ac1.x); ac1.y = fmaf(q1p, vv.y, ac1.y);
            ac2.x = fmaf(q2p, vv.x, ac2.x); ac2.y = fmaf(q2p, vv.y, ac2.y);
            ac3.x = fmaf(q3p, vv.x, ac3.x); ac3.y = fmaf(q3p, vv.y, ac3.y);
        }
    }
    float2 accs[4] = {ac0, ac1, ac2, ac3};
    float dens[4] = {den0, den1, den2, den3};
    #pragma unroll
    for (int i = 0; i < 4; i++) {
        int t = t0 + i;
        if (t < qcount) {
            float inv = 1.f / dens[i];
            float2 o = make_float2(accs[i].x*inv, accs[i].y*inv);
            *(float2*)&g_CTX[(size_t)(b*qcount + t)*DD + h*DHH + lane*2] = o;
        }
    }
}

__global__ void latent_update_kernel(int slot) {
    int idx = blockIdx.x * blockDim.x + threadIdx.x;
    if (idx >= BB*DD) return;
    int b = idx / DD, d = idx - b*DD;
    g_embeds[((size_t)b*SS + slot)*DD + d] = g_HID[((size_t)b*SS + (slot - 1))*DD + d];
}

__global__ void loss_row_kernel(const float* __restrict__ logits, const int* __restrict__ labels) {
    int r = blockIdx.x;
    int b = r / (SS-1), t = r - b*(SS-1);
    const float* x = logits + ((size_t)(b*SS + t))*VV;
    int tid = threadIdx.x;
    __shared__ float sh[8];
    float mx = -1e30f;
    for (int i = tid; i < VV; i += 256) mx = fmaxf(mx, x[i]);
    mx = warpReduceMax(mx);
    if ((tid & 31) == 0) sh[tid >> 5] = mx;
    __syncthreads();
    if (tid == 0) { float m = sh[0]; for (int i = 1; i < 8; i++) m = fmaxf(m, sh[i]); sh[0] = m; }
    __syncthreads();
    mx = sh[0];
    __syncthreads();
    float se = 0.f;
    for (int i = tid; i < VV; i += 256) se += __expf(x[i] - mx);
    se = warpReduceSum(se);
    if ((tid & 31) == 0) sh[tid >> 5] = se;
    __syncthreads();
    if (tid == 0) {
        float s = 0.f; for (int i = 0; i < 8; i++) s += sh[i];
        int lab = labels[b*SS + t + 1];
        g_nll[r] = logf(s) + mx - x[lab];
    }
}
__global__ void loss_final_kernel(float* out) {
    int tid = threadIdx.x;
    const int NR = BB*(SS-1);
    __shared__ float sh[8];
    float s = 0.f;
    for (int i = tid; i < NR; i += 256) s += g_nll[i];
    s = warpReduceSum(s);
    if ((tid & 31) == 0) sh[tid >> 5] = s;
    __syncthreads();
    if (tid == 0) {
        float t = 0.f; for (int i = 0; i < 8; i++) t += sh[i];
        out[0] = t / (float)NR;
    }
}

static int pick_z(int nx, int ny) {
    int z = 1;
    while (z < 8 && nx*ny*z < 148) z *= 2;
    return z;
}

extern "C" void kernel_launch(void* const* d_in, const int* in_sizes, int n_in,
                              void* d_out, int out_size) {
    const int*   input_ids = (const int*)d_in[0];
    const int*   amask     = (const int*)d_in[1];
    const int*   labels    = (const int*)d_in[2];
    const int*   pos_ids   = (const int*)d_in[3];
    const float* wte   = (const float*)d_in[4];
    const float* wpe   = (const float*)d_in[5];
    const float* ln1_g = (const float*)d_in[6];
    const float* ln1_b = (const float*)d_in[7];
    const float* Wqkv  = (const float*)d_in[8];
    const float* bqkv  = (const float*)d_in[9];
    const float* Wo    = (const float*)d_in[10];
    const float* bo    = (const float*)d_in[11];
    const float* ln2_g = (const float*)d_in[12];
    const float* ln2_b = (const float*)d_in[13];
    const float* W1    = (const float*)d_in[14];
    const float* b1    = (const float*)d_in[15];
    const float* W2    = (const float*)d_in[16];
    const float* b2    = (const float*)d_in[17];
    const float* lnf_g = (const float*)d_in[18];
    const float* lnf_b = (const float*)d_in[19];

    float* out    = (float*)d_out;
    float* logits = out + 1;

    float *pX, *pH, *pHID, *pQKV, *pCTX, *pG, *pWT;
    cudaGetSymbolAddress((void**)&pX,   g_X);
    cudaGetSymbolAddress((void**)&pH,   g_H);
    cudaGetSymbolAddress((void**)&pHID, g_HID);
    cudaGetSymbolAddress((void**)&pQKV, g_QKV);
    cudaGetSymbolAddress((void**)&pCTX, g_CTX);
    cudaGetSymbolAddress((void**)&pG,   g_G);
    cudaGetSymbolAddress((void**)&pWT,  g_wteT);

    embed_init_kernel<<<(BB*SS*DD + 255)/256, 256>>>(input_ids, wte);
    transpose_wte_kernel<<<dim3(VPAD/32, DD/32), dim3(32, 8)>>>(wte);

    const int QS[7] = {0, 64, 65, 66, 67, 68, 69};
    const int QC[7] = {64, 1,  1,  1,  1,  1,  SS - 69};

    for (int p = 0; p < 7; p++) {
        int qs = QS[p], qc = QC[p];
        int M = BB * qc;

        build_x_kernel<<<(M*DD + 255)/256, 256>>>(pos_ids, wpe, qs, qc);

        for (int l = 0; l < NLAYER; l++) {
            const float* Wq  = Wqkv + (size_t)l*DD*3*DD;  const float* bq  = bqkv + (size_t)l*3*DD;
            const float* Wol = Wo   + (size_t)l*DD*DD;    const float* bol = bo   + (size_t)l*DD;
            const float* W1l = W1   + (size_t)l*DD*DFFN;  const float* b1l = b1   + (size_t)l*DFFN;
            const float* W2l = W2   + (size_t)l*DFFN*DD;  const float* b2l = b2   + (size_t)l*DD;

            ln_kernel<<<M, 256>>>(pX, pH, ln1_g + l*DD, ln1_b + l*DD, qc, qs, 0);

            if (qc == 1) {
                gemv4_part<<<dim3(3*DD/128, DD/128), 128>>>(pH, Wq, 3*DD, DD);
                gemv4_red<0,0><<<(3*DD + 255)/256, 256>>>(bq, 0, pQKV, 3*DD, DD/128);
            } else {
                int ny = (M + 127)/128;
                int z = pick_z(18, ny);
                if (z == 1) {
                    gemm128<0,0,1><<<dim3(18, ny), 256>>>(pH, Wq, bq, 0, pQKV, M, 3*DD, DD, 3*DD, 3*DD);
                } else {
                    gemm128<0,0,0><<<dim3(18, ny, z), 256>>>(pH, Wq, 0, 0, pQKV, M, 3*DD, DD, 3*DD, 3*DD);
                    gemmred<0,0><<<(M*3*DD + 255)/256, 256>>>(bq, 0, pQKV, M, 3*DD, z);
                }
            }

            kv_scatter<<<(M*DD + 255)/256, 256>>>(l, qs, qc);

            int nqt = (qc + 3)/4;
            attn_kernel<<<(nqt*BB*HH + 7)/8, 256>>>(l, qs, qc, amask);

            if (qc == 1) {
                gemv4_part<<<dim3(DD/128, DD/128), 128>>>(pCTX, Wol, DD, DD);
                gemv4_red<0,1><<<(DD + 255)/256, 256>>>(bol, pX, pX, DD, DD/128);
            } else {
                int ny = (M + 127)/128;
                int z = pick_z(6, ny);
                if (z == 1) {
                    gemm128<0,1,1><<<dim3(6, ny), 256>>>(pCTX, Wol, bol, pX, pX, M, DD, DD, DD, DD);
                } else {
                    gemm128<0,0,0><<<dim3(6, ny, z), 256>>>(pCTX, Wol, 0, 0, pX, M, DD, DD, DD, DD);
                    gemmred<0,1><<<(M*DD + 255)/256, 256>>>(bol, pX, pX, M, DD, z);
                }
            }

            ln_kernel<<<M, 256>>>(pX, pH, ln2_g + l*DD, ln2_b + l*DD, qc, qs, 0);

            if (qc == 1) {
                gemv4_part<<<dim3(DFFN/128, DD/128), 128>>>(pH, W1l, DFFN, DD);
                gemv4_red<1,0><<<(DFFN + 255)/256, 256>>>(b1l, 0, pG, DFFN, DD/128);
                gemv4_part<<<dim3(DD/128, DFFN/128), 128>>>(pG, W2l, DD, DFFN);
                gemv4_red<0,1><<<(DD + 255)/256, 256>>>(b2l, pX, pX, DD, DFFN/128);
            } else {
                int ny = (M + 127)/128;
                int z1 = pick_z(24, ny);
                if (z1 == 1) {
                    gemm128<1,0,1><<<dim3(24, ny), 256>>>(pH, W1l, b1l, 0, pG, M, DFFN, DD, DFFN, DFFN);
                } else {
                    gemm128<0,0,0><<<dim3(24, ny, z1), 256>>>(pH, W1l, 0, 0, pG, M, DFFN, DD, DFFN, DFFN);
                    gemmred<1,0><<<(M*DFFN + 255)/256, 256>>>(b1l, 0, pG, M, DFFN, z1);
                }
                int z2 = pick_z(6, ny);
                if (z2 == 1) {
                    gemm128<0,1,1><<<dim3(6, ny), 256>>>(pG, W2l, b2l, pX, pX, M, DD, DFFN, DD, DD);
                } else {
                    gemm128<0,0,0><<<dim3(6, ny, z2), 256>>>(pG, W2l, 0, 0, pX, M, DD, DFFN, DD, DD);
                    gemmred<0,1><<<(M*DD + 255)/256, 256>>>(b2l, pX, pX, M, DD, z2);
                }
            }
        }

        ln_kernel<<<M, 256>>>(pX, pHID, lnf_g, lnf_b, qc, qs, 1);

        if (p < NLAT) {
            latent_update_kernel<<<(BB*DD + 255)/256, 256>>>(LAT_START + p);
        }
    }

    gemm128<0,0,0><<<dim3(VPAD/128, (BB*SS)/128), 256>>>(pHID, pWT, 0, 0, logits,
                                                          BB*SS, VV, DD, VPAD, VV);

    loss_row_kernel<<<BB*(SS-1), 256>>>(logits, labels);
    loss_final_kernel<<<1, 256>>>(out);
}

// round 14
// speedup vs baseline: 2.5005x; 1.2879x over previous
#include <cuda_runtime.h>
#include <cuda_bf16.h>
#include <mma.h>
#include <stdint.h>
#include <math.h>

using namespace nvcuda;

#define BB 4
#define SS 512
#define VV 50257
#define DD 768
#define HH 12
#define DHH 64
#define NLAYER 2
#define DFFN 3072
#define LAT_START 64
#define NLAT 6
#define ATT_SCALE 0.125f

#define WQKV_T_OFF 0
#define WO_T_OFF   (2304*768)
#define W1_T_OFF   (2304*768 + 768*768)
#define W2_T_OFF   (2304*768 + 768*768 + 3072*768)
#define PER_L      (2304*768 + 768*768 + 3072*768 + 768*3072)
#define TG_SMEM    81920
#define LDS_A 40
#define ABUF (128*LDS_A)

static __device__ float g_embeds[BB*SS*DD];
static __device__ float g_X   [BB*SS*DD];
static __device__ float g_H   [BB*SS*DD];
static __device__ float g_HID [BB*SS*DD];
static __device__ float g_QKV [BB*SS*3*DD];
static __device__ float g_CTX [BB*SS*DD];
static __device__ float g_G   [BB*SS*DFFN];
static __device__ float g_K   [NLAYER*BB*HH*SS*DHH];
static __device__ float g_V   [NLAYER*BB*HH*SS*DHH];
static __device__ float g_part[24*4*DFFN];
static __device__ float g_nll [BB*(SS-1)];
static __device__ __align__(16) __nv_bfloat16 g_Whi[2*PER_L];
static __device__ __align__(16) __nv_bfloat16 g_Wlo[2*PER_L];
static __device__ __align__(16) __nv_bfloat16 g_Vhi[(size_t)VV*DD];
static __device__ __align__(16) __nv_bfloat16 g_Vlo[(size_t)VV*DD];
static __device__ __align__(16) __nv_bfloat16 g_Ahi[BB*SS*DFFN];
static __device__ __align__(16) __nv_bfloat16 g_Alo[BB*SS*DFFN];

__device__ __forceinline__ float wrsum(float v) {
    #pragma unroll
    for (int o = 16; o; o >>= 1) v += __shfl_xor_sync(0xffffffffu, v, o);
    return v;
}
__device__ __forceinline__ float wrmax(float v) {
    #pragma unroll
    for (int o = 16; o; o >>= 1) v = fmaxf(v, __shfl_xor_sync(0xffffffffu, v, o));
    return v;
}
__device__ __forceinline__ float gelu_tanh(float u) {
    return 0.5f*u*(1.f + tanhf(0.7978845608028654f*(u + 0.044715f*u*u*u)));
}

__global__ void cvt_split(const float* __restrict__ s, __nv_bfloat16* __restrict__ hi,
                          __nv_bfloat16* __restrict__ lo, int n) {
    int i = blockIdx.x * 256 + threadIdx.x;
    if (i >= n) return;
    float v = s[i];
    __nv_bfloat16 h = __float2bfloat16(v);
    hi[i] = h;
    lo[i] = __float2bfloat16(v - __bfloat162float(h));
}

__global__ void cvt_tr(const float* __restrict__ W, __nv_bfloat16* __restrict__ hiT,
                       __nv_bfloat16* __restrict__ loT, int K, int N) {
    __shared__ float t[32][33];
    int k0 = blockIdx.y * 32, n0 = blockIdx.x * 32;
    for (int i = threadIdx.y; i < 32; i += 8)
        t[i][threadIdx.x] = W[(size_t)(k0 + i)*N + n0 + threadIdx.x];
    __syncthreads();
    for (int i = threadIdx.y; i < 32; i += 8) {
        int n = n0 + i, k = k0 + threadIdx.x;
        float v = t[threadIdx.x][i];
        __nv_bfloat16 h = __float2bfloat16(v);
        hiT[(size_t)n*K + k] = h;
        loT[(size_t)n*K + k] = __float2bfloat16(v - __bfloat162float(h));
    }
}

// HMMA (wmma bf16) split-bf16 GEMM. C[M,N]=epi(A x B^T). B is [N,K] row-major.
// Tile 128x128, 8 warps of 64x32, K chunks of 32, double-buffered.
template<int ACT, int HASRES, int HASBIAS>
__global__ void __launch_bounds__(256, 1)
tgemm(const __nv_bfloat16* __restrict__ Ah, const __nv_bfloat16* __restrict__ Al,
      const __nv_bfloat16* __restrict__ Bh, const __nv_bfloat16* __restrict__ Bl,
      const float* __restrict__ bias, const float* __restrict__ res,
      float* __restrict__ C, int M, int N, int K, int ldc) {
    extern __shared__ __align__(16) __nv_bfloat16 smem[];
    int tid = threadIdx.x, wid = tid >> 5, lane = tid & 31;
    int row0 = blockIdx.x * 128, col0 = blockIdx.y * 128;
    int wm = wid >> 2, wn = wid & 3;        // warp tile: rows wm*64, cols wn*32

    wmma::fragment<wmma::accumulator, 16, 16, 16, float> acc[4][2];
    #pragma unroll
    for (int m = 0; m < 4; m++)
        #pragma unroll
        for (int n = 0; n < 2; n++) wmma::fill_fragment(acc[m][n], 0.0f);

    int KC = K >> 5;

    // preload chunk 0 into buffer 0
    {
        int kc = 0, b = 0;
        for (int i = tid; i < 1024; i += 256) {   // A hi|lo: 2 x 128 x 32
            int var = i >> 9, e = i & 511, r = e >> 2, g = e & 3;
            int gr = row0 + r;
            uint4 v = make_uint4(0,0,0,0);
            const __nv_bfloat16* s = var ? Al : Ah;
            if (gr < M) v = *(const uint4*)(s + (size_t)gr*K + kc*32 + g*8);
            *(uint4*)(smem + b*4*ABUF + var*ABUF + r*LDS_A + g*8) = v;
        }
        for (int i = tid; i < 1024; i += 256) {   // B hi|lo
            int var = i >> 9, e = i & 511, r = e >> 2, g = e & 3;
            int gn = col0 + r;
            uint4 v = make_uint4(0,0,0,0);
            const __nv_bfloat16* s = var ? Bl : Bh;
            if (gn < N) v = *(const uint4*)(s + (size_t)gn*K + kc*32 + g*8);
            *(uint4*)(smem + b*4*ABUF + (2 + var)*ABUF + r*LDS_A + g*8) = v;
        }
    }
    __syncthreads();

    for (int kc = 0; kc < KC; kc++) {
        int b = kc & 1;
        // prefetch next chunk into regs
        uint4 pa[4], pb[4];
        if (kc + 1 < KC) {
            #pragma unroll
            for (int j = 0; j < 4; j++) {
                int i = tid + j*256;
                int var = i >> 9, e = i & 511, r = e >> 2, g = e & 3;
                int gr = row0 + r;
                pa[j] = make_uint4(0,0,0,0);
                const __nv_bfloat16* s = var ? Al : Ah;
                if (gr < M) pa[j] = *(const uint4*)(s + (size_t)gr*K + (kc+1)*32 + g*8);
                int gn = col0 + r;
                pb[j] = make_uint4(0,0,0,0);
                const __nv_bfloat16* s2 = var ? Bl : Bh;
                if (gn < N) pb[j] = *(const uint4*)(s2 + (size_t)gn*K + (kc+1)*32 + g*8);
            }
        }

        const __nv_bfloat16* bufp = smem + b*4*ABUF;
        #pragma unroll
        for (int ks = 0; ks < 2; ks++) {
            wmma::fragment<wmma::matrix_b, 16, 16, 16, __nv_bfloat16, wmma::col_major> fbh[2], fbl[2];
            #pragma unroll
            for (int n = 0; n < 2; n++) {
                const __nv_bfloat16* pBh = bufp + 2*ABUF + (wn*32 + n*16)*LDS_A + ks*16;
                const __nv_bfloat16* pBl = bufp + 3*ABUF + (wn*32 + n*16)*LDS_A + ks*16;
                wmma::load_matrix_sync(fbh[n], pBh, LDS_A);
                wmma::load_matrix_sync(fbl[n], pBl, LDS_A);
            }
            #pragma unroll
            for (int m = 0; m < 4; m++) {
                wmma::fragment<wmma::matrix_a, 16, 16, 16, __nv_bfloat16, wmma::row_major> fah, fal;
                const __nv_bfloat16* pAh = bufp + 0*ABUF + (wm*64 + m*16)*LDS_A + ks*16;
                const __nv_bfloat16* pAl = bufp + 1*ABUF + (wm*64 + m*16)*LDS_A + ks*16;
                wmma::load_matrix_sync(fah, pAh, LDS_A);
                wmma::load_matrix_sync(fal, pAl, LDS_A);
                #pragma unroll
                for (int n = 0; n < 2; n++) {
                    wmma::mma_sync(acc[m][n], fah, fbh[n], acc[m][n]);
                    wmma::mma_sync(acc[m][n], fah, fbl[n], acc[m][n]);
                    wmma::mma_sync(acc[m][n], fal, fbh[n], acc[m][n]);
                }
            }
        }

        if (kc + 1 < KC) {
            int nb = (kc + 1) & 1;
            #pragma unroll
            for (int j = 0; j < 4; j++) {
                int i = tid + j*256;
                int var = i >> 9, e = i & 511, r = e >> 2, g = e & 3;
                *(uint4*)(smem + nb*4*ABUF + var*ABUF + r*LDS_A + g*8) = pa[j];
                *(uint4*)(smem + nb*4*ABUF + (2 + var)*ABUF + r*LDS_A + g*8) = pb[j];
            }
        }
        __syncthreads();
    }

    // epilogue: store accs to smem (float, stride 36), then fused writes
    float* fsm = (float*)smem;
    float* wsm = fsm + wid * (64*36);
    #pragma unroll
    for (int m = 0; m < 4; m++)
        #pragma unroll
        for (int n = 0; n < 2; n++)
            wmma::store_matrix_sync(wsm + m*16*36 + n*16, acc[m][n], 36, wmma::mem_row_major);
    __syncwarp();
    int cc = lane;
    int gc = col0 + wn*32 + cc;
    if (gc < N) {
        float bv = HASBIAS ? bias[gc] : 0.f;
        for (int rr = 0; rr < 64; rr++) {
            int gr = row0 + wm*64 + rr;
            if (gr >= M) break;
            float v = wsm[rr*36 + cc] ;
            if (HASBIAS) v += bv;
            if (ACT)     v = gelu_tanh(v);
            if (HASRES)  v += res[(size_t)gr*ldc + gc];
            C[(size_t)gr*ldc + gc] = v;
        }
    }
}

__global__ void embed_init_kernel(const int* __restrict__ ids, const float* __restrict__ wte) {
    int idx = blockIdx.x * 256 + threadIdx.x;
    if (idx >= BB*SS*DD) return;
    int r = idx / DD, d = idx - r*DD;
    g_embeds[idx] = wte[(size_t)ids[r]*DD + d];
}
__global__ void build_x_kernel(const int* __restrict__ pos_ids, const float* __restrict__ wpe,
                               int qs, int qc) {
    int idx = blockIdx.x * 256 + threadIdx.x;
    if (idx >= BB*qc*DD) return;
    int r = idx / DD, d = idx - r*DD;
    int b = r / qc, t = r - b*qc;
    int s = qs + t;
    g_X[idx] = g_embeds[((size_t)b*SS + s)*DD + d] + wpe[(size_t)pos_ids[b*SS + s]*DD + d];
}
__global__ void ln_kernel(const float* __restrict__ in, float* __restrict__ out,
                          const float* __restrict__ gam, const float* __restrict__ bet,
                          int qc, int qs, int scatter) {
    int r = blockIdx.x;
    const float* x = in + (size_t)r*DD;
    int tid = threadIdx.x;
    float x0 = x[tid], x1 = x[tid+256], x2 = x[tid+512];
    __shared__ float sh[8];
    float s = wrsum(x0 + x1 + x2);
    if ((tid & 31) == 0) sh[tid >> 5] = s;
    __syncthreads();
    if (tid == 0) { float t = 0.f; for (int i = 0; i < 8; i++) t += sh[i]; sh[0] = t * (1.f/DD); }
    __syncthreads();
    float mean = sh[0];
    float d0 = x0 - mean, d1 = x1 - mean, d2 = x2 - mean;
    __syncthreads();
    float q = wrsum(d0*d0 + d1*d1 + d2*d2);
    if ((tid & 31) == 0) sh[tid >> 5] = q;
    __syncthreads();
    if (tid == 0) { float t = 0.f; for (int i = 0; i < 8; i++) t += sh[i]; sh[0] = rsqrtf(t*(1.f/DD) + 1e-5f); }
    __syncthreads();
    float rstd = sh[0];
    int orow = r;
    if (scatter) { int b = r / qc, t = r - b*qc; orow = b*SS + qs + t; }
    float* o = out + (size_t)orow*DD;
    o[tid]     = d0*rstd*gam[tid]     + bet[tid];
    o[tid+256] = d1*rstd*gam[tid+256] + bet[tid+256];
    o[tid+512] = d2*rstd*gam[tid+512] + bet[tid+512];
}

__global__ void gemv4_part(const float* __restrict__ A, const float* __restrict__ W, int N, int K) {
    __shared__ float Ash[4][128];
    int tid = threadIdx.x;
    int k0 = blockIdx.y * 128;
    for (int i = tid; i < 512; i += 128) {
        int r = i >> 7, k = i & 127;
        Ash[r][k] = A[(size_t)r*K + k0 + k];
    }
    __syncthreads();
    int n = blockIdx.x * 128 + tid;
    const float* wp = W + (size_t)k0*N + n;
    float s0=0.f, s1=0.f, s2=0.f, s3=0.f;
    #pragma unroll 8
    for (int k = 0; k < 128; k++) {
        float w = wp[(size_t)k*N];
        s0 = fmaf(w, Ash[0][k], s0);
        s1 = fmaf(w, Ash[1][k], s1);
        s2 = fmaf(w, Ash[2][k], s2);
        s3 = fmaf(w, Ash[3][k], s3);
    }
    float* pp = g_part + (size_t)blockIdx.y*4*DFFN + n;
    pp[0] = s0; pp[DFFN] = s1; pp[2*DFFN] = s2; pp[3*DFFN] = s3;
}
template<int ACT, int HASRES>
__global__ void gemv4_red(const float* __restrict__ bias, const float* __restrict__ res,
                          float* __restrict__ C, int N, int kch) {
    int n = blockIdx.x * 256 + threadIdx.x;
    if (n >= N) return;
    #pragma unroll
    for (int r = 0; r < 4; r++) {
        float s = bias[n];
        for (int c = 0; c < kch; c++) s += g_part[(size_t)c*4*DFFN + r*DFFN + n];
        if (ACT)    s = gelu_tanh(s);
        if (HASRES) s += res[(size_t)r*N + n];
        C[(size_t)r*N + n] = s;
    }
}

__global__ void kv_scatter(int l, int qs, int qc) {
    int idx = blockIdx.x * 256 + threadIdx.x;
    if (idx >= BB*qc*DD) return;
    int r = idx / DD, d = idx - r*DD;
    int b = r / qc, t = r - b*qc;
    int h = d >> 6, dh = d & 63;
    size_t c = ((size_t)((l*BB + b)*HH + h)*SS + qs + t)*DHH + dh;
    g_K[c] = g_QKV[(size_t)r*(3*DD) + DD   + d];
    g_V[c] = g_QKV[(size_t)r*(3*DD) + 2*DD + d];
}

__global__ void attn_kernel(int l, int qs, int qc, const int* __restrict__ amask) {
    __shared__ float qsh[8][4][64];
    int w = threadIdx.x >> 5, lane = threadIdx.x & 31;
    int nqt = (qc + 3) >> 2;
    int gw = blockIdx.x * 8 + w;
    if (gw >= nqt * BB * HH) return;
    int h = gw % HH, r1 = gw / HH, b = r1 % BB, qt = r1 / BB;
    int t0 = qt * 4;
    #pragma unroll
    for (int i = 0; i < 4; i++) {
        int t = t0 + i; if (t >= qc) t = qc - 1;
        const float* qp = g_QKV + (size_t)(b*qc + t)*(3*DD) + h*DHH;
        qsh[w][i][lane]      = qp[lane]      * ATT_SCALE;
        qsh[w][i][lane + 32] = qp[lane + 32] * ATT_SCALE;
    }
    __syncwarp();
    int qlast = min(t0 + 3, qc - 1);
    int qmax = qs + qlast;
    const float* kc = g_K + (size_t)((l*BB + b)*HH + h)*SS*DHH;
    const float* vc = g_V + (size_t)((l*BB + b)*HH + h)*SS*DHH;
    float m0=-1e30f,m1=-1e30f,m2=-1e30f,m3=-1e30f, dn0=0.f,dn1=0.f,dn2=0.f,dn3=0.f;
    float2 a0={0.f,0.f},a1={0.f,0.f},a2={0.f,0.f},a3={0.f,0.f};
    for (int j0 = 0; j0 <= qmax; j0 += 32) {
        int j = j0 + lane;
        float s0=-1e30f,s1=-1e30f,s2=-1e30f,s3=-1e30f;
        if (j <= qmax && amask[b*SS + j] != 0) {
            const float4* kr = (const float4*)(kc + (size_t)j*DHH);
            float u0=0.f,u1=0.f,u2=0.f,u3=0.f;
            #pragma unroll
            for (int i2 = 0; i2 < 16; i2++) {
                float4 kv = kr[i2];
                float4 q0 = *(const float4*)&qsh[w][0][i2*4];
                float4 q1 = *(const float4*)&qsh[w][1][i2*4];
                float4 q2 = *(const float4*)&qsh[w][2][i2*4];
                float4 q3 = *(const float4*)&qsh[w][3][i2*4];
                u0 += kv.x*q0.x + kv.y*q0.y + kv.z*q0.z + kv.w*q0.w;
                u1 += kv.x*q1.x + kv.y*q1.y + kv.z*q1.z + kv.w*q1.w;
                u2 += kv.x*q2.x + kv.y*q2.y + kv.z*q2.z + kv.w*q2.w;
                u3 += kv.x*q3.x + kv.y*q3.y + kv.z*q3.z + kv.w*q3.w;
            }
            s0 = (j <= qs + t0    ) ? u0 : -1e30f;
            s1 = (j <= qs + t0 + 1) ? u1 : -1e30f;
            s2 = (j <= qs + t0 + 2) ? u2 : -1e30f;
            s3 = (j <= qs + t0 + 3) ? u3 : -1e30f;
        }
        float n0 = fmaxf(m0, wrmax(s0)), n1 = fmaxf(m1, wrmax(s1));
        float n2 = fmaxf(m2, wrmax(s2)), n3 = fmaxf(m3, wrmax(s3));
        float p0 = __expf(s0-n0), p1 = __expf(s1-n1), p2 = __expf(s2-n2), p3 = __expf(s3-n3);
        float q0 = wrsum(p0), q1 = wrsum(p1), q2 = wrsum(p2), q3 = wrsum(p3);
        float e0 = __expf(m0-n0), e1 = __expf(m1-n1), e2 = __expf(m2-n2), e3 = __expf(m3-n3);
        dn0 = dn0*e0 + q0; a0.x *= e0; a0.y *= e0; m0 = n0;
        dn1 = dn1*e1 + q1; a1.x *= e1; a1.y *= e1; m1 = n1;
        dn2 = dn2*e2 + q2; a2.x *= e2; a2.y *= e2; m2 = n2;
        dn3 = dn3*e3 + q3; a3.x *= e3; a3.y *= e3; m3 = n3;
        int jc = min(32, qmax - j0 + 1);
        for (int jj = 0; jj < jc; jj++) {
            float2 vv = *(const float2*)(vc + (size_t)(j0 + jj)*DHH + lane*2);
            float w0 = __shfl_sync(0xffffffffu, p0, jj), w1 = __shfl_sync(0xffffffffu, p1, jj);
            float w2 = __shfl_sync(0xffffffffu, p2, jj), w3 = __shfl_sync(0xffffffffu, p3, jj);
            a0.x = fmaf(w0, vv.x, a0.x); a0.y = fmaf(w0, vv.y, a0.y);
            a1.x = fmaf(w1, vv.x, a1.x); a1.y = fmaf(w1, vv.y, a1.y);
            a2.x = fmaf(w2, vv.x, a2.x); a2.y = fmaf(w2, vv.y, a2.y);
            a3.x = fmaf(w3, vv.x, a3.x); a3.y = fmaf(w3, vv.y, a3.y);
        }
    }
    float2 ac[4] = {a0,a1,a2,a3};
    float dn[4] = {dn0,dn1,dn2,dn3};
    #pragma unroll
    for (int i = 0; i < 4; i++) {
        int t = t0 + i;
        if (t < qc) {
            float inv = 1.f / dn[i];
            *(float2*)&g_CTX[(size_t)(b*qc + t)*DD + h*DHH + lane*2] =
                make_float2(ac[i].x*inv, ac[i].y*inv);
        }
    }
}

__global__ void latent_update_kernel(int slot) {
    int idx = blockIdx.x * 256 + threadIdx.x;
    if (idx >= BB*DD) return;
    int b = idx / DD, d = idx - b*DD;
    g_embeds[((size_t)b*SS + slot)*DD + d] = g_HID[((size_t)b*SS + slot - 1)*DD + d];
}

__global__ void loss_row_kernel(const float* __restrict__ logits, const int* __restrict__ labels) {
    int r = blockIdx.x;
    int b = r / (SS-1), t = r - b*(SS-1);
    const float* x = logits + ((size_t)(b*SS + t))*VV;
    int tid = threadIdx.x;
    __shared__ float sh[8];
    float mx = -1e30f;
    for (int i = tid; i < VV; i += 256) mx = fmaxf(mx, x[i]);
    mx = wrmax(mx);
    if ((tid & 31) == 0) sh[tid >> 5] = mx;
    __syncthreads();
    if (tid == 0) { float m = sh[0]; for (int i = 1; i < 8; i++) m = fmaxf(m, sh[i]); sh[0] = m; }
    __syncthreads();
    mx = sh[0];
    __syncthreads();
    float se = 0.f;
    for (int i = tid; i < VV; i += 256) se += __expf(x[i] - mx);
    se = wrsum(se);
    if ((tid & 31) == 0) sh[tid >> 5] = se;
    __syncthreads();
    if (tid == 0) {
        float s = 0.f; for (int i = 0; i < 8; i++) s += sh[i];
        g_nll[r] = logf(s) + mx - x[labels[b*SS + t + 1]];
    }
}
__global__ void loss_final_kernel(float* out) {
    int tid = threadIdx.x;
    __shared__ float sh[8];
    float s = 0.f;
    for (int i = tid; i < BB*(SS-1); i += 256) s += g_nll[i];
    s = wrsum(s);
    if ((tid & 31) == 0) sh[tid >> 5] = s;
    __syncthreads();
    if (tid == 0) {
        float t = 0.f; for (int i = 0; i < 8; i++) t += sh[i];
        out[0] = t / (float)(BB*(SS-1));
    }
}

extern "C" void kernel_launch(void* const* d_in, const int* in_sizes, int n_in,
                              void* d_out, int out_size) {
    const int*   input_ids = (const int*)d_in[0];
    const int*   amask     = (const int*)d_in[1];
    const int*   labels    = (const int*)d_in[2];
    const int*   pos_ids   = (const int*)d_in[3];
    const float* wte   = (const float*)d_in[4];
    const float* wpe   = (const float*)d_in[5];
    const float* ln1_g = (const float*)d_in[6];
    const float* ln1_b = (const float*)d_in[7];
    const float* Wqkv  = (const float*)d_in[8];
    const float* bqkv  = (const float*)d_in[9];
    const float* Wo    = (const float*)d_in[10];
    const float* bo    = (const float*)d_in[11];
    const float* ln2_g = (const float*)d_in[12];
    const float* ln2_b = (const float*)d_in[13];
    const float* W1    = (const float*)d_in[14];
    const float* b1    = (const float*)d_in[15];
    const float* W2    = (const float*)d_in[16];
    const float* b2    = (const float*)d_in[17];
    const float* lnf_g = (const float*)d_in[18];
    const float* lnf_b = (const float*)d_in[19];

    float* out    = (float*)d_out;
    float* logits = out + 1;

    cudaFuncSetAttribute(tgemm<0,0,0>, cudaFuncAttributeMaxDynamicSharedMemorySize, TG_SMEM);
    cudaFuncSetAttribute(tgemm<0,0,1>, cudaFuncAttributeMaxDynamicSharedMemorySize, TG_SMEM);
    cudaFuncSetAttribute(tgemm<0,1,1>, cudaFuncAttributeMaxDynamicSharedMemorySize, TG_SMEM);
    cudaFuncSetAttribute(tgemm<1,0,1>, cudaFuncAttributeMaxDynamicSharedMemorySize, TG_SMEM);

    float *pX, *pH, *pHID, *pQKV, *pCTX, *pG;
    cudaGetSymbolAddress((void**)&pX,   g_X);
    cudaGetSymbolAddress((void**)&pH,   g_H);
    cudaGetSymbolAddress((void**)&pHID, g_HID);
    cudaGetSymbolAddress((void**)&pQKV, g_QKV);
    cudaGetSymbolAddress((void**)&pCTX, g_CTX);
    cudaGetSymbolAddress((void**)&pG,   g_G);
    __nv_bfloat16 *pAh, *pAl, *pWh, *pWl, *pVh, *pVl;
    cudaGetSymbolAddress((void**)&pAh, g_Ahi);
    cudaGetSymbolAddress((void**)&pAl, g_Alo);
    cudaGetSymbolAddress((void**)&pWh, g_Whi);
    cudaGetSymbolAddress((void**)&pWl, g_Wlo);
    cudaGetSymbolAddress((void**)&pVh, g_Vhi);
    cudaGetSymbolAddress((void**)&pVl, g_Vlo);

    embed_init_kernel<<<(BB*SS*DD + 255)/256, 256>>>(input_ids, wte);
    cvt_split<<<(VV*DD + 255)/256, 256>>>(wte, pVh, pVl, VV*DD);
    for (int l = 0; l < NLAYER; l++) {
        __nv_bfloat16* wh = pWh + (size_t)l*PER_L;
        __nv_bfloat16* wl = pWl + (size_t)l*PER_L;
        cvt_tr<<<dim3(2304/32, 768/32),  dim3(32,8)>>>(Wqkv + (size_t)l*DD*3*DD, wh + WQKV_T_OFF, wl + WQKV_T_OFF, 768, 2304);
        cvt_tr<<<dim3(768/32,  768/32),  dim3(32,8)>>>(Wo   + (size_t)l*DD*DD,   wh + WO_T_OFF,   wl + WO_T_OFF,   768, 768);
        cvt_tr<<<dim3(3072/32, 768/32),  dim3(32,8)>>>(W1   + (size_t)l*DD*DFFN, wh + W1_T_OFF,   wl + W1_T_OFF,   768, 3072);
        cvt_tr<<<dim3(768/32,  3072/32), dim3(32,8)>>>(W2   + (size_t)l*DFFN*DD, wh + W2_T_OFF,   wl + W2_T_OFF,   3072, 768);
    }

    const int QS[7] = {0, 64, 65, 66, 67, 68, 69};
    const int QC[7] = {64, 1,  1,  1,  1,  1,  SS - 69};

    for (int p = 0; p < 7; p++) {
        int qs = QS[p], qc = QC[p];
        int M = BB * qc;
        int mt = (M + 127)/128;

        build_x_kernel<<<(M*DD + 255)/256, 256>>>(pos_ids, wpe, qs, qc);

        for (int l = 0; l < NLAYER; l++) {
            __nv_bfloat16* wh = pWh + (size_t)l*PER_L;
            __nv_bfloat16* wl = pWl + (size_t)l*PER_L;
            const float* Wq  = Wqkv + (size_t)l*DD*3*DD;  const float* bq  = bqkv + (size_t)l*3*DD;
            const float* Wol = Wo   + (size_t)l*DD*DD;    const float* bol = bo   + (size_t)l*DD;
            const float* W1l = W1   + (size_t)l*DD*DFFN;  const float* b1l = b1   + (size_t)l*DFFN;
            const float* W2l = W2   + (size_t)l*DFFN*DD;  const float* b2l = b2   + (size_t)l*DD;

            ln_kernel<<<M, 256>>>(pX, pH, ln1_g + l*DD, ln1_b + l*DD, qc, qs, 0);

            if (qc == 1) {
                gemv4_part<<<dim3(3*DD/128, DD/128), 128>>>(pH, Wq, 3*DD, DD);
                gemv4_red<0,0><<<(3*DD + 255)/256, 256>>>(bq, 0, pQKV, 3*DD, DD/128);
            } else {
                cvt_split<<<(M*DD + 255)/256, 256>>>(pH, pAh, pAl, M*DD);
                tgemm<0,0,1><<<dim3(mt, 18), 256, TG_SMEM>>>(pAh, pAl, wh + WQKV_T_OFF, wl + WQKV_T_OFF,
                                                             bq, 0, pQKV, M, 3*DD, DD, 3*DD);
            }

            kv_scatter<<<(M*DD + 255)/256, 256>>>(l, qs, qc);
            attn_kernel<<<(((qc+3)/4)*BB*HH + 7)/8, 256>>>(l, qs, qc, amask);

            if (qc == 1) {
                gemv4_part<<<dim3(DD/128, DD/128), 128>>>(pCTX, Wol, DD, DD);
                gemv4_red<0,1><<<(DD + 255)/256, 256>>>(bol, pX, pX, DD, DD/128);
            } else {
                cvt_split<<<(M*DD + 255)/256, 256>>>(pCTX, pAh, pAl, M*DD);
                tgemm<0,1,1><<<dim3(mt, 6), 256, TG_SMEM>>>(pAh, pAl, wh + WO_T_OFF, wl + WO_T_OFF,
                                                            bol, pX, pX, M, DD, DD, DD);
            }

            ln_kernel<<<M, 256>>>(pX, pH, ln2_g + l*DD, ln2_b + l*DD, qc, qs, 0);

            if (qc == 1) {
                gemv4_part<<<dim3(DFFN/128, DD/128), 128>>>(pH, W1l, DFFN, DD);
                gemv4_red<1,0><<<(DFFN + 255)/256, 256>>>(b1l, 0, pG, DFFN, DD/128);
                gemv4_part<<<dim3(DD/128, DFFN/128), 128>>>(pG, W2l, DD, DFFN);
                gemv4_red<0,1><<<(DD + 255)/256, 256>>>(b2l, pX, pX, DD, DFFN/128);
            } else {
                cvt_split<<<(M*DD + 255)/256, 256>>>(pH, pAh, pAl, M*DD);
                tgemm<1,0,1><<<dim3(mt, 24), 256, TG_SMEM>>>(pAh, pAl, wh + W1_T_OFF, wl + W1_T_OFF,
                                                             b1l, 0, pG, M, DFFN, DD, DFFN);
                cvt_split<<<(M*DFFN + 255)/256, 256>>>(pG, pAh, pAl, M*DFFN);
                tgemm<0,1,1><<<dim3(mt, 6), 256, TG_SMEM>>>(pAh, pAl, wh + W2_T_OFF, wl + W2_T_OFF,
                                                            b2l, pX, pX, M, DD, DFFN, DD);
            }
        }

        ln_kernel<<<M, 256>>>(pX, pHID, lnf_g, lnf_b, qc, qs, 1);

        if (p < NLAT) latent_update_kernel<<<(BB*DD + 255)/256, 256>>>(LAT_START + p);
    }

    cvt_split<<<(BB*SS*DD + 255)/256, 256>>>(pHID, pAh, pAl, BB*SS*DD);
    tgemm<0,0,0><<<dim3(BB*SS/128, (VV + 127)/128), 256, TG_SMEM>>>(pAh, pAl, pVh, pVl,
                                                                    0, 0, logits, BB*SS, VV, DD, VV);

    loss_row_kernel<<<BB*(SS-1), 256>>>(logits, labels);
    loss_final_kernel<<<1, 256>>>(out);
}